// round 3
// baseline (speedup 1.0000x reference)
#include <cuda_runtime.h>
#include <cuda_bf16.h>
#include <math.h>

// ---------------- Problem constants ----------------
#define BB   8
#define TT   12
#define NN   883
#define DD   128
#define HH   8
#define CC   16
#define EE   7000
#define FFD  2048
#define NEG_SLOPE 0.2f

#define BT      (BB*TT)                 // 96
#define TNODES  (BT*NN)                 // 84768
#define ETOT    (BT*EE + TNODES)        // 756768
#define FFCHUNK 512
#define NCHUNKS (FFD/FFCHUNK)           // 4

// ---------------- Device scratch (allowed: __device__ globals) ----------------
__device__ float g_xl[(size_t)TNODES * DD];
__device__ float g_xr[(size_t)TNODES * DD];
__device__ float g_score[(size_t)ETOT * HH];
__device__ float g_smax[(size_t)TNODES * HH];
__device__ float g_denom[(size_t)TNODES * HH];
__device__ float g_agg[(size_t)TNODES * DD];
__device__ float g_h[(size_t)TNODES * DD];
__device__ float g_hid[(size_t)TNODES * FFCHUNK];
__device__ int   g_is64;   // 1 if edge_index buffer is int64, 0 if int32

// ---------------- Helpers ----------------
__device__ __forceinline__ void atomicMaxFloat(float* addr, float value) {
    if (value >= 0.0f)
        atomicMax((int*)addr, __float_as_int(value));
    else
        atomicMin((unsigned int*)addr, __float_as_uint(value));
}

// ---------------- Detect edge_index element width ----------------
// int64 little-endian with values in [0,883): every odd 32-bit word is 0.
// Genuine int32 index data has random values at odd words.
__global__ void detect_kernel(const int* __restrict__ ei32) {
    if (threadIdx.x == 0 && blockIdx.x == 0) {
        int ok = 1;
        #pragma unroll
        for (int i = 1; i < 64; i += 2) ok &= (ei32[i] == 0);
        g_is64 = ok;
    }
}

// ---------------- Init scratch ----------------
__global__ void init_kernel() {
    int i = blockIdx.x * blockDim.x + threadIdx.x;
    if (i < TNODES * DD) g_agg[i] = 0.0f;
    if (i < TNODES * HH) {
        g_smax[i]  = __int_as_float(0xff800000); // -inf
        g_denom[i] = 0.0f;
    }
}

// ---------------- Generic tiled SGEMM: C = op(A*B [+bias]) [+C] ----------------
template<bool RELU, bool BIAS, bool ACCUM>
__global__ __launch_bounds__(256)
void sgemm(const float* __restrict__ A, int lda,
           const float* __restrict__ B, int ldb,
           const float* __restrict__ bias,
           float* __restrict__ C, int ldc,
           int M, int N, int K)
{
    const int BM = 128, BN = 128, BK = 16, TM = 8, TNt = 8;
    __shared__ float As[BK][BM];
    __shared__ float Bs[BK][BN];

    int tid = threadIdx.x;
    int tx = tid & 15;
    int ty = tid >> 4;
    int m0 = blockIdx.y * BM;
    int n0 = blockIdx.x * BN;

    float acc[TM][TNt];
    #pragma unroll
    for (int i = 0; i < TM; i++)
        #pragma unroll
        for (int j = 0; j < TNt; j++) acc[i][j] = 0.0f;

    int aRow = tid >> 2;          // 0..63
    int aCol = (tid & 3) * 4;     // 0,4,8,12
    int bRow = tid >> 5;          // 0..7
    int bCol = (tid & 31) * 4;    // 0..124

    for (int k0 = 0; k0 < K; k0 += BK) {
        #pragma unroll
        for (int r = 0; r < 2; r++) {
            int ml = aRow + r * 64;
            int m = m0 + ml;
            float4 v = make_float4(0.f, 0.f, 0.f, 0.f);
            if (m < M) v = *(const float4*)&A[(size_t)m * lda + k0 + aCol];
            As[aCol + 0][ml] = v.x;
            As[aCol + 1][ml] = v.y;
            As[aCol + 2][ml] = v.z;
            As[aCol + 3][ml] = v.w;
        }
        #pragma unroll
        for (int r = 0; r < 2; r++) {
            int kk = bRow + r * 8;
            float4 v = *(const float4*)&B[(size_t)(k0 + kk) * ldb + n0 + bCol];
            *(float4*)&Bs[kk][bCol] = v;
        }
        __syncthreads();

        #pragma unroll
        for (int k = 0; k < BK; k++) {
            float4 a0 = *(const float4*)&As[k][ty * TM];
            float4 a1 = *(const float4*)&As[k][ty * TM + 4];
            float4 b0 = *(const float4*)&Bs[k][tx * TNt];
            float4 b1 = *(const float4*)&Bs[k][tx * TNt + 4];
            float af[TM] = {a0.x, a0.y, a0.z, a0.w, a1.x, a1.y, a1.z, a1.w};
            float bf[TNt] = {b0.x, b0.y, b0.z, b0.w, b1.x, b1.y, b1.z, b1.w};
            #pragma unroll
            for (int i = 0; i < TM; i++)
                #pragma unroll
                for (int j = 0; j < TNt; j++)
                    acc[i][j] = fmaf(af[i], bf[j], acc[i][j]);
        }
        __syncthreads();
    }

    #pragma unroll
    for (int i = 0; i < TM; i++) {
        int m = m0 + ty * TM + i;
        if (m >= M) continue;
        #pragma unroll
        for (int j = 0; j < TNt; j++) {
            int n = n0 + tx * TNt + j;
            float v = acc[i][j];
            if (BIAS) v += bias[n];
            if (RELU) v = fmaxf(v, 0.0f);
            if (ACCUM) v += C[(size_t)m * ldc + n];
            C[(size_t)m * ldc + n] = v;
        }
    }
}

// ---------------- Edge decode (dtype-robust, clamped) ----------------
__device__ __forceinline__ int load_ei(const int* __restrict__ ei32, int is64, int idx) {
    int v = is64 ? ei32[2 * idx] : ei32[idx];
    v = v < 0 ? 0 : (v >= NN ? NN - 1 : v);   // clamp: crash-proof, errors surface as rel_err
    return v;
}

__device__ __forceinline__ void edge_decode(int e, const int* __restrict__ ei32,
                                            int is64, int& src, int& dst)
{
    if (e < BT * EE) {
        int inst = e / EE;
        int idx  = e - inst * EE;
        int base = inst * NN;
        src = load_ei(ei32, is64, idx) + base;
        dst = load_ei(ei32, is64, EE + idx) + base;
    } else {
        src = dst = e - BT * EE;
    }
}

// ---------------- Pass A: scores + segment max ----------------
__global__ void edge_score_kernel(const int* __restrict__ ei32,
                                  const float* __restrict__ att)
{
    int t = blockIdx.x * blockDim.x + threadIdx.x;
    if (t >= ETOT * HH) return;
    int e = t >> 3;
    int h = t & 7;
    int is64 = g_is64;
    int src, dst;
    edge_decode(e, ei32, is64, src, dst);

    const float4* xl = (const float4*)&g_xl[(size_t)src * DD + h * CC];
    const float4* xr = (const float4*)&g_xr[(size_t)dst * DD + h * CC];
    const float4* at = (const float4*)&att[h * CC];

    float s = 0.0f;
    #pragma unroll
    for (int q = 0; q < 4; q++) {
        float4 a = xl[q];
        float4 b = xr[q];
        float4 w = at[q];
        float v0 = a.x + b.x; v0 = v0 > 0.f ? v0 : NEG_SLOPE * v0;
        float v1 = a.y + b.y; v1 = v1 > 0.f ? v1 : NEG_SLOPE * v1;
        float v2 = a.z + b.z; v2 = v2 > 0.f ? v2 : NEG_SLOPE * v2;
        float v3 = a.w + b.w; v3 = v3 > 0.f ? v3 : NEG_SLOPE * v3;
        s = fmaf(w.x, v0, s);
        s = fmaf(w.y, v1, s);
        s = fmaf(w.z, v2, s);
        s = fmaf(w.w, v3, s);
    }
    g_score[t] = s;
    atomicMaxFloat(&g_smax[(size_t)dst * HH + h], s);
}

// ---------------- Pass B: exp + segment sum ----------------
__global__ void edge_exp_kernel(const int* __restrict__ ei32)
{
    int t = blockIdx.x * blockDim.x + threadIdx.x;
    if (t >= ETOT * HH) return;
    int e = t >> 3;
    int h = t & 7;
    int is64 = g_is64;
    int src, dst;
    edge_decode(e, ei32, is64, src, dst);
    float a = expf(g_score[t] - g_smax[(size_t)dst * HH + h]);
    g_score[t] = a;
    atomicAdd(&g_denom[(size_t)dst * HH + h], a);
}

// ---------------- Pass C: weighted scatter-add aggregation ----------------
__global__ void edge_agg_kernel(const int* __restrict__ ei32)
{
    long long t = (long long)blockIdx.x * blockDim.x + threadIdx.x;
    if (t >= (long long)ETOT * 32) return;   // (edge, head, quad-of-4)
    int e = (int)(t >> 5);
    int r = (int)(t & 31);
    int h = r >> 2;
    int q = r & 3;
    int is64 = g_is64;
    int src, dst;
    edge_decode(e, ei32, is64, src, dst);
    float alpha = g_score[(size_t)e * HH + h] / g_denom[(size_t)dst * HH + h];
    float4 xlv = *(const float4*)&g_xl[(size_t)src * DD + h * CC + q * 4];
    float* out = &g_agg[(size_t)dst * DD + h * CC + q * 4];
    atomicAdd(out + 0, alpha * xlv.x);
    atomicAdd(out + 1, alpha * xlv.y);
    atomicAdd(out + 2, alpha * xlv.z);
    atomicAdd(out + 3, alpha * xlv.w);
}

// ---------------- LayerNorm 1: h = LN(x + agg + bias_gat) ----------------
__global__ void ln1_kernel(const float* __restrict__ x,
                           const float* __restrict__ bias_gat,
                           const float* __restrict__ g,
                           const float* __restrict__ b)
{
    int row = blockIdx.x * 8 + (threadIdx.x >> 5);
    if (row >= TNODES) return;
    int lane = threadIdx.x & 31;
    size_t base = (size_t)row * DD + lane * 4;

    float4 xv = *(const float4*)&x[base];
    float4 av = *(const float4*)&g_agg[base];
    float4 bg = *(const float4*)&bias_gat[lane * 4];
    float v[4] = {xv.x + av.x + bg.x, xv.y + av.y + bg.y,
                  xv.z + av.z + bg.z, xv.w + av.w + bg.w};

    float s = v[0] + v[1] + v[2] + v[3];
    #pragma unroll
    for (int o = 16; o > 0; o >>= 1) s += __shfl_xor_sync(0xffffffffu, s, o);
    float mu = s * (1.0f / DD);

    float sq = 0.f;
    #pragma unroll
    for (int i = 0; i < 4; i++) { float d = v[i] - mu; sq += d * d; }
    #pragma unroll
    for (int o = 16; o > 0; o >>= 1) sq += __shfl_xor_sync(0xffffffffu, sq, o);
    float rstd = rsqrtf(sq * (1.0f / DD) + 1e-5f);

    float4 gv = *(const float4*)&g[lane * 4];
    float4 bv = *(const float4*)&b[lane * 4];
    float4 o4;
    o4.x = (v[0] - mu) * rstd * gv.x + bv.x;
    o4.y = (v[1] - mu) * rstd * gv.y + bv.y;
    o4.z = (v[2] - mu) * rstd * gv.z + bv.z;
    o4.w = (v[3] - mu) * rstd * gv.w + bv.w;
    *(float4*)&g_h[base] = o4;
}

// ---------------- LayerNorm 2: out = LN(h + ff) (ff staged in d_out) ----------------
__global__ void ln2_kernel(float* __restrict__ out,
                           const float* __restrict__ g,
                           const float* __restrict__ b)
{
    int row = blockIdx.x * 8 + (threadIdx.x >> 5);
    if (row >= TNODES) return;
    int lane = threadIdx.x & 31;
    size_t base = (size_t)row * DD + lane * 4;

    float4 hv = *(const float4*)&g_h[base];
    float4 fv = *(const float4*)&out[base];
    float v[4] = {hv.x + fv.x, hv.y + fv.y, hv.z + fv.z, hv.w + fv.w};

    float s = v[0] + v[1] + v[2] + v[3];
    #pragma unroll
    for (int o = 16; o > 0; o >>= 1) s += __shfl_xor_sync(0xffffffffu, s, o);
    float mu = s * (1.0f / DD);

    float sq = 0.f;
    #pragma unroll
    for (int i = 0; i < 4; i++) { float d = v[i] - mu; sq += d * d; }
    #pragma unroll
    for (int o = 16; o > 0; o >>= 1) sq += __shfl_xor_sync(0xffffffffu, sq, o);
    float rstd = rsqrtf(sq * (1.0f / DD) + 1e-5f);

    float4 gv = *(const float4*)&g[lane * 4];
    float4 bv = *(const float4*)&b[lane * 4];
    float4 o4;
    o4.x = (v[0] - mu) * rstd * gv.x + bv.x;
    o4.y = (v[1] - mu) * rstd * gv.y + bv.y;
    o4.z = (v[2] - mu) * rstd * gv.z + bv.z;
    o4.w = (v[3] - mu) * rstd * gv.w + bv.w;
    *(float4*)&out[base] = o4;
}

// ---------------- Launch ----------------
extern "C" void kernel_launch(void* const* d_in, const int* in_sizes, int n_in,
                              void* d_out, int out_size)
{
    const float* x        = (const float*)d_in[0];
    const int*   ei32     = (const int*)d_in[1];   // int32 or int64 words; detected on device
    const float* Wl       = (const float*)d_in[2];
    const float* bl       = (const float*)d_in[3];
    const float* Wr       = (const float*)d_in[4];
    const float* br       = (const float*)d_in[5];
    const float* att      = (const float*)d_in[6];
    const float* bias_gat = (const float*)d_in[7];
    const float* W1       = (const float*)d_in[8];
    const float* b1       = (const float*)d_in[9];
    const float* W2       = (const float*)d_in[10];
    const float* b2       = (const float*)d_in[11];
    const float* g1       = (const float*)d_in[12];
    const float* be1      = (const float*)d_in[13];
    const float* g2       = (const float*)d_in[14];
    const float* be2      = (const float*)d_in[15];
    float*       out      = (float*)d_out;

    float *p_xl, *p_xr, *p_h, *p_hid;
    cudaGetSymbolAddress((void**)&p_xl,  g_xl);
    cudaGetSymbolAddress((void**)&p_xr,  g_xr);
    cudaGetSymbolAddress((void**)&p_h,   g_h);
    cudaGetSymbolAddress((void**)&p_hid, g_hid);

    const int M = TNODES;
    const int MB = (M + 127) / 128;   // 663

    detect_kernel<<<1, 32>>>(ei32);

    {
        int n = TNODES * DD;
        init_kernel<<<(n + 255) / 256, 256>>>();
    }

    // x_l = x @ Wl + bl ; x_r = x @ Wr + br
    {
        dim3 grid(1, MB);
        sgemm<false, true, false><<<grid, 256>>>(x, DD, Wl, DD, bl, p_xl, DD, M, DD, DD);
        sgemm<false, true, false><<<grid, 256>>>(x, DD, Wr, DD, br, p_xr, DD, M, DD, DD);
    }

    // edge passes
    {
        long long tA = (long long)ETOT * HH;
        edge_score_kernel<<<(unsigned)((tA + 255) / 256), 256>>>(ei32, att);
        edge_exp_kernel<<<(unsigned)((tA + 255) / 256), 256>>>(ei32);
        long long tC = (long long)ETOT * 32;
        edge_agg_kernel<<<(unsigned)((tC + 255) / 256), 256>>>(ei32);
    }

    // LN1
    ln1_kernel<<<(TNODES + 7) / 8, 256>>>(x, bias_gat, g1, be1);

    // FFN, chunked over FF dim (4 x 512); ff accumulates into d_out
    for (int c = 0; c < NCHUNKS; c++) {
        dim3 grid1(FFCHUNK / 128, MB);
        sgemm<true, true, false><<<grid1, 256>>>(p_h, DD, W1 + c * FFCHUNK, FFD,
                                                 b1 + c * FFCHUNK, p_hid, FFCHUNK,
                                                 M, FFCHUNK, DD);
        dim3 grid2(1, MB);
        if (c == 0)
            sgemm<false, true, false><<<grid2, 256>>>(p_hid, FFCHUNK,
                                                      W2 + (size_t)c * FFCHUNK * DD, DD,
                                                      b2, out, DD, M, DD, FFCHUNK);
        else
            sgemm<false, false, true><<<grid2, 256>>>(p_hid, FFCHUNK,
                                                      W2 + (size_t)c * FFCHUNK * DD, DD,
                                                      nullptr, out, DD, M, DD, FFCHUNK);
    }

    // LN2 -> final output
    ln2_kernel<<<(TNODES + 7) / 8, 256>>>(out, g2, be2);
}

// round 5
// speedup vs baseline: 1.4838x; 1.4838x over previous
#include <cuda_runtime.h>
#include <cuda_bf16.h>
#include <math.h>
#include <stdint.h>

// ---------------- Problem constants ----------------
#define BB   8
#define TT   12
#define NN   883
#define DD   128
#define HH   8
#define CC   16
#define EE   7000
#define FFD  2048
#define NEG_SLOPE 0.2f

#define BT      (BB*TT)                 // 96
#define TNODES  (BT*NN)                 // 84768
#define ETOT    (BT*EE + TNODES)        // 756768

// ---------------- Device scratch ----------------
__device__ float g_xl[(size_t)TNODES * DD];
__device__ float g_xr[(size_t)TNODES * DD];
__device__ float g_score[(size_t)ETOT * HH];
__device__ float g_smax[(size_t)TNODES * HH];
__device__ float g_denom[(size_t)TNODES * HH];
__device__ float g_agg[(size_t)TNODES * DD];
__device__ float g_h[(size_t)TNODES * DD];
__device__ float g_hid[(size_t)TNODES * FFD];   // fp32 FFN intermediate
__device__ int   g_is64;

// ---------------- Small helpers ----------------
__device__ __forceinline__ uint32_t smem_to_u32(const void* p) {
    uint32_t a;
    asm("{ .reg .u64 t; cvta.to.shared.u64 t, %1; cvt.u32.u64 %0, t; }"
        : "=r"(a) : "l"(p));
    return a;
}
__device__ __forceinline__ void ldsm_x4(uint32_t& r0, uint32_t& r1,
                                        uint32_t& r2, uint32_t& r3, uint32_t addr) {
    asm volatile("ldmatrix.sync.aligned.m8n8.x4.shared.b16 {%0,%1,%2,%3}, [%4];"
        : "=r"(r0), "=r"(r1), "=r"(r2), "=r"(r3) : "r"(addr));
}
__device__ __forceinline__ void ldsm_x2(uint32_t& r0, uint32_t& r1, uint32_t addr) {
    asm volatile("ldmatrix.sync.aligned.m8n8.x2.shared.b16 {%0,%1}, [%2];"
        : "=r"(r0), "=r"(r1) : "r"(addr));
}
__device__ __forceinline__ void mma_bf16(float* c,
                                         uint32_t a0, uint32_t a1, uint32_t a2, uint32_t a3,
                                         uint32_t b0, uint32_t b1) {
    asm volatile("mma.sync.aligned.m16n8k16.row.col.f32.bf16.bf16.f32 "
        "{%0,%1,%2,%3}, {%4,%5,%6,%7}, {%8,%9}, {%0,%1,%2,%3};"
        : "+f"(c[0]), "+f"(c[1]), "+f"(c[2]), "+f"(c[3])
        : "r"(a0), "r"(a1), "r"(a2), "r"(a3), "r"(b0), "r"(b1));
}
__device__ __forceinline__ __nv_bfloat16 bf_hi(float v) { return __float2bfloat16_rn(v); }

// ---------------- bf16-split tensor-core GEMM (mma.sync, sm_80 path) ----------
// C[M,N] = op(A[M,K] @ B[K,N] + bias)
// grid = (N/128, ceil(M/128)), block = 256 (8 warps, 2x4 warp grid, 64x32 each)
#define SROW 40   // smem row stride (elements) -> 80B rows, ldmatrix conflict-free

template<bool RELU, bool BIAS>
__global__ __launch_bounds__(256)
void gemm_mma(const float* __restrict__ A, int lda,
              const float* __restrict__ B, int ldb,
              const float* __restrict__ bias,
              float* __restrict__ C, int ldc,
              int M, int K)
{
    __shared__ __nv_bfloat16 sAh[128][SROW];
    __shared__ __nv_bfloat16 sAl[128][SROW];
    __shared__ __nv_bfloat16 sBh[128][SROW];   // [n][k]
    __shared__ __nv_bfloat16 sBl[128][SROW];

    const int tid  = threadIdx.x;
    const int wid  = tid >> 5;
    const int lane = tid & 31;
    const int m0 = blockIdx.y * 128;
    const int n0 = blockIdx.x * 128;

    const int warp_m = (wid >> 2) * 64;     // 0 or 64
    const int warp_n = (wid & 3) * 32;      // 0,32,64,96

    float c[4][4][4];
    #pragma unroll
    for (int i = 0; i < 4; i++)
        #pragma unroll
        for (int j = 0; j < 4; j++)
            #pragma unroll
            for (int r = 0; r < 4; r++) c[i][j][r] = 0.0f;

    const uint32_t uAh = smem_to_u32(&sAh[0][0]);
    const uint32_t uAl = smem_to_u32(&sAl[0][0]);
    const uint32_t uBh = smem_to_u32(&sBh[0][0]);
    const uint32_t uBl = smem_to_u32(&sBl[0][0]);

    // ldmatrix per-lane address components
    const int a_row_l = lane & 15;            // row within 16-row frag
    const int a_colh  = (lane >> 4) * 8;      // k-half
    const int l16     = lane & 15;
    const int b_row_l = l16 & 7;              // n-row within 8
    const int b_colh  = ((l16 >> 3) & 1) * 8; // k-half

    // B gmem load mapping: n fixed per thread, 16 k's
    const int bn  = tid & 127;
    const int bk0 = (tid >> 7) * 16;

    const int nk = K >> 5;   // BK = 32

    for (int kc = 0; kc < nk; kc++) {
        const int kbase = kc << 5;

        // ---- A tile 128x32 fp32 -> split bf16 ----
        #pragma unroll
        for (int r = 0; r < 4; r++) {
            int f4 = tid + r * 256;          // 0..1023
            int row = f4 >> 3;
            int c4  = (f4 & 7) * 4;
            int m = m0 + row;
            float4 v = make_float4(0.f, 0.f, 0.f, 0.f);
            if (m < M) v = *(const float4*)&A[(size_t)m * lda + kbase + c4];
            __nv_bfloat16 h0 = bf_hi(v.x), h1 = bf_hi(v.y), h2 = bf_hi(v.z), h3 = bf_hi(v.w);
            sAh[row][c4 + 0] = h0; sAh[row][c4 + 1] = h1;
            sAh[row][c4 + 2] = h2; sAh[row][c4 + 3] = h3;
            sAl[row][c4 + 0] = bf_hi(v.x - __bfloat162float(h0));
            sAl[row][c4 + 1] = bf_hi(v.y - __bfloat162float(h1));
            sAl[row][c4 + 2] = bf_hi(v.z - __bfloat162float(h2));
            sAl[row][c4 + 3] = bf_hi(v.w - __bfloat162float(h3));
        }
        // ---- B tile 32x128 fp32 -> split bf16, transposed to [n][k] ----
        #pragma unroll
        for (int k = 0; k < 16; k++) {
            int kk = bk0 + k;
            float v = B[(size_t)(kbase + kk) * ldb + n0 + bn];
            __nv_bfloat16 h = bf_hi(v);
            sBh[bn][kk] = h;
            sBl[bn][kk] = bf_hi(v - __bfloat162float(h));
        }
        __syncthreads();

        // ---- MMA phase ----
        #pragma unroll
        for (int kk = 0; kk < 32; kk += 16) {
            uint32_t ah[4][4], al[4][4], bh[4][2], bl[4][2];
            #pragma unroll
            for (int i = 0; i < 4; i++) {
                uint32_t off = ((uint32_t)((warp_m + i * 16 + a_row_l) * SROW + a_colh + kk)) * 2;
                ldsm_x4(ah[i][0], ah[i][1], ah[i][2], ah[i][3], uAh + off);
                ldsm_x4(al[i][0], al[i][1], al[i][2], al[i][3], uAl + off);
            }
            #pragma unroll
            for (int j = 0; j < 4; j++) {
                uint32_t off = ((uint32_t)((warp_n + j * 8 + b_row_l) * SROW + b_colh + kk)) * 2;
                ldsm_x2(bh[j][0], bh[j][1], uBh + off);
                ldsm_x2(bl[j][0], bl[j][1], uBl + off);
            }
            #pragma unroll
            for (int i = 0; i < 4; i++)
                #pragma unroll
                for (int j = 0; j < 4; j++) {
                    mma_bf16(c[i][j], ah[i][0], ah[i][1], ah[i][2], ah[i][3],
                             bh[j][0], bh[j][1]);
                    mma_bf16(c[i][j], ah[i][0], ah[i][1], ah[i][2], ah[i][3],
                             bl[j][0], bl[j][1]);
                    mma_bf16(c[i][j], al[i][0], al[i][1], al[i][2], al[i][3],
                             bh[j][0], bh[j][1]);
                }
        }
        __syncthreads();
    }

    // ---- epilogue: direct gmem store (float2 per half-frag) ----
    #pragma unroll
    for (int j = 0; j < 4; j++) {
        int col = n0 + warp_n + j * 8 + (lane & 3) * 2;
        float bx = 0.f, by = 0.f;
        if (BIAS) { bx = bias[col]; by = bias[col + 1]; }
        #pragma unroll
        for (int i = 0; i < 4; i++) {
            int row = m0 + warp_m + i * 16 + (lane >> 2);
            float v0 = c[i][j][0] + bx, v1 = c[i][j][1] + by;
            float v2 = c[i][j][2] + bx, v3 = c[i][j][3] + by;
            if (RELU) {
                v0 = fmaxf(v0, 0.f); v1 = fmaxf(v1, 0.f);
                v2 = fmaxf(v2, 0.f); v3 = fmaxf(v3, 0.f);
            }
            if (row < M)     *(float2*)&C[(size_t)row * ldc + col]       = make_float2(v0, v1);
            if (row + 8 < M) *(float2*)&C[(size_t)(row + 8) * ldc + col] = make_float2(v2, v3);
        }
    }
}

// ---------------- Edge machinery (proven in R3) ----------------
__device__ __forceinline__ void atomicMaxFloat(float* addr, float value) {
    if (value >= 0.0f)
        atomicMax((int*)addr, __float_as_int(value));
    else
        atomicMin((unsigned int*)addr, __float_as_uint(value));
}

__global__ void detect_kernel(const int* __restrict__ ei32) {
    if (threadIdx.x == 0 && blockIdx.x == 0) {
        int ok = 1;
        #pragma unroll
        for (int i = 1; i < 64; i += 2) ok &= (ei32[i] == 0);
        g_is64 = ok;
    }
}

__global__ void init_kernel() {
    int i = blockIdx.x * blockDim.x + threadIdx.x;
    if (i < TNODES * DD) g_agg[i] = 0.0f;
    if (i < TNODES * HH) {
        g_smax[i]  = __int_as_float(0xff800000);
        g_denom[i] = 0.0f;
    }
}

__device__ __forceinline__ int load_ei(const int* __restrict__ ei32, int is64, int idx) {
    int v = is64 ? ei32[2 * idx] : ei32[idx];
    v = v < 0 ? 0 : (v >= NN ? NN - 1 : v);
    return v;
}

__device__ __forceinline__ void edge_decode(int e, const int* __restrict__ ei32,
                                            int is64, int& src, int& dst)
{
    if (e < BT * EE) {
        int inst = e / EE;
        int idx  = e - inst * EE;
        int base = inst * NN;
        src = load_ei(ei32, is64, idx) + base;
        dst = load_ei(ei32, is64, EE + idx) + base;
    } else {
        src = dst = e - BT * EE;
    }
}

__global__ void edge_score_kernel(const int* __restrict__ ei32,
                                  const float* __restrict__ att)
{
    int t = blockIdx.x * blockDim.x + threadIdx.x;
    if (t >= ETOT * HH) return;
    int e = t >> 3;
    int h = t & 7;
    int is64 = g_is64;
    int src, dst;
    edge_decode(e, ei32, is64, src, dst);

    const float4* xl = (const float4*)&g_xl[(size_t)src * DD + h * CC];
    const float4* xr = (const float4*)&g_xr[(size_t)dst * DD + h * CC];
    const float4* at = (const float4*)&att[h * CC];

    float s = 0.0f;
    #pragma unroll
    for (int q = 0; q < 4; q++) {
        float4 a = xl[q];
        float4 b = xr[q];
        float4 w = at[q];
        float v0 = a.x + b.x; v0 = v0 > 0.f ? v0 : NEG_SLOPE * v0;
        float v1 = a.y + b.y; v1 = v1 > 0.f ? v1 : NEG_SLOPE * v1;
        float v2 = a.z + b.z; v2 = v2 > 0.f ? v2 : NEG_SLOPE * v2;
        float v3 = a.w + b.w; v3 = v3 > 0.f ? v3 : NEG_SLOPE * v3;
        s = fmaf(w.x, v0, s);
        s = fmaf(w.y, v1, s);
        s = fmaf(w.z, v2, s);
        s = fmaf(w.w, v3, s);
    }
    g_score[t] = s;
    atomicMaxFloat(&g_smax[(size_t)dst * HH + h], s);
}

__global__ void edge_exp_kernel(const int* __restrict__ ei32)
{
    int t = blockIdx.x * blockDim.x + threadIdx.x;
    if (t >= ETOT * HH) return;
    int e = t >> 3;
    int h = t & 7;
    int is64 = g_is64;
    int src, dst;
    edge_decode(e, ei32, is64, src, dst);
    float a = expf(g_score[t] - g_smax[(size_t)dst * HH + h]);
    g_score[t] = a;
    atomicAdd(&g_denom[(size_t)dst * HH + h], a);
}

__global__ void edge_agg_kernel(const int* __restrict__ ei32)
{
    long long t = (long long)blockIdx.x * blockDim.x + threadIdx.x;
    if (t >= (long long)ETOT * 32) return;
    int e = (int)(t >> 5);
    int r = (int)(t & 31);
    int h = r >> 2;
    int q = r & 3;
    int is64 = g_is64;
    int src, dst;
    edge_decode(e, ei32, is64, src, dst);
    float alpha = g_score[(size_t)e * HH + h] / g_denom[(size_t)dst * HH + h];
    float4 xlv = *(const float4*)&g_xl[(size_t)src * DD + h * CC + q * 4];
    float* out = &g_agg[(size_t)dst * DD + h * CC + q * 4];
    atomicAdd(out + 0, alpha * xlv.x);
    atomicAdd(out + 1, alpha * xlv.y);
    atomicAdd(out + 2, alpha * xlv.z);
    atomicAdd(out + 3, alpha * xlv.w);
}

// ---------------- LayerNorms ----------------
__global__ void ln1_kernel(const float* __restrict__ x,
                           const float* __restrict__ bias_gat,
                           const float* __restrict__ g,
                           const float* __restrict__ b)
{
    int row = blockIdx.x * 8 + (threadIdx.x >> 5);
    if (row >= TNODES) return;
    int lane = threadIdx.x & 31;
    size_t base = (size_t)row * DD + lane * 4;

    float4 xv = *(const float4*)&x[base];
    float4 av = *(const float4*)&g_agg[base];
    float4 bg = *(const float4*)&bias_gat[lane * 4];
    float v[4] = {xv.x + av.x + bg.x, xv.y + av.y + bg.y,
                  xv.z + av.z + bg.z, xv.w + av.w + bg.w};

    float s = v[0] + v[1] + v[2] + v[3];
    #pragma unroll
    for (int o = 16; o > 0; o >>= 1) s += __shfl_xor_sync(0xffffffffu, s, o);
    float mu = s * (1.0f / DD);

    float sq = 0.f;
    #pragma unroll
    for (int i = 0; i < 4; i++) { float d = v[i] - mu; sq += d * d; }
    #pragma unroll
    for (int o = 16; o > 0; o >>= 1) sq += __shfl_xor_sync(0xffffffffu, sq, o);
    float rstd = rsqrtf(sq * (1.0f / DD) + 1e-5f);

    float4 gv = *(const float4*)&g[lane * 4];
    float4 bv = *(const float4*)&b[lane * 4];
    float4 o4;
    o4.x = (v[0] - mu) * rstd * gv.x + bv.x;
    o4.y = (v[1] - mu) * rstd * gv.y + bv.y;
    o4.z = (v[2] - mu) * rstd * gv.z + bv.z;
    o4.w = (v[3] - mu) * rstd * gv.w + bv.w;
    *(float4*)&g_h[base] = o4;
}

__global__ void ln2_kernel(float* __restrict__ out,
                           const float* __restrict__ g,
                           const float* __restrict__ b)
{
    int row = blockIdx.x * 8 + (threadIdx.x >> 5);
    if (row >= TNODES) return;
    int lane = threadIdx.x & 31;
    size_t base = (size_t)row * DD + lane * 4;

    float4 hv = *(const float4*)&g_h[base];
    float4 fv = *(const float4*)&out[base];
    float v[4] = {hv.x + fv.x, hv.y + fv.y, hv.z + fv.z, hv.w + fv.w};

    float s = v[0] + v[1] + v[2] + v[3];
    #pragma unroll
    for (int o = 16; o > 0; o >>= 1) s += __shfl_xor_sync(0xffffffffu, s, o);
    float mu = s * (1.0f / DD);

    float sq = 0.f;
    #pragma unroll
    for (int i = 0; i < 4; i++) { float d = v[i] - mu; sq += d * d; }
    #pragma unroll
    for (int o = 16; o > 0; o >>= 1) sq += __shfl_xor_sync(0xffffffffu, sq, o);
    float rstd = rsqrtf(sq * (1.0f / DD) + 1e-5f);

    float4 gv = *(const float4*)&g[lane * 4];
    float4 bv = *(const float4*)&b[lane * 4];
    float4 o4;
    o4.x = (v[0] - mu) * rstd * gv.x + bv.x;
    o4.y = (v[1] - mu) * rstd * gv.y + bv.y;
    o4.z = (v[2] - mu) * rstd * gv.z + bv.z;
    o4.w = (v[3] - mu) * rstd * gv.w + bv.w;
    *(float4*)&out[base] = o4;
}

// ---------------- Launch ----------------
extern "C" void kernel_launch(void* const* d_in, const int* in_sizes, int n_in,
                              void* d_out, int out_size)
{
    const float* x        = (const float*)d_in[0];
    const int*   ei32     = (const int*)d_in[1];
    const float* Wl       = (const float*)d_in[2];
    const float* bl       = (const float*)d_in[3];
    const float* Wr       = (const float*)d_in[4];
    const float* br       = (const float*)d_in[5];
    const float* att      = (const float*)d_in[6];
    const float* bias_gat = (const float*)d_in[7];
    const float* W1       = (const float*)d_in[8];
    const float* b1       = (const float*)d_in[9];
    const float* W2       = (const float*)d_in[10];
    const float* b2       = (const float*)d_in[11];
    const float* g1       = (const float*)d_in[12];
    const float* be1      = (const float*)d_in[13];
    const float* g2       = (const float*)d_in[14];
    const float* be2      = (const float*)d_in[15];
    float*       out      = (float*)d_out;

    float *p_xl, *p_xr, *p_h, *p_hid;
    cudaGetSymbolAddress((void**)&p_xl,  g_xl);
    cudaGetSymbolAddress((void**)&p_xr,  g_xr);
    cudaGetSymbolAddress((void**)&p_h,   g_h);
    cudaGetSymbolAddress((void**)&p_hid, g_hid);

    const int M  = TNODES;
    const int MB = (M + 127) / 128;   // 663

    detect_kernel<<<1, 32>>>(ei32);
    {
        int n = TNODES * DD;
        init_kernel<<<(n + 255) / 256, 256>>>();
    }

    // projections: x_l = x@Wl + bl ; x_r = x@Wr + br
    {
        dim3 grid(1, MB);
        gemm_mma<false, true><<<grid, 256>>>(x, DD, Wl, DD, bl, p_xl, DD, M, DD);
        gemm_mma<false, true><<<grid, 256>>>(x, DD, Wr, DD, br, p_xr, DD, M, DD);
    }

    // edge passes
    {
        long long tA = (long long)ETOT * HH;
        edge_score_kernel<<<(unsigned)((tA + 255) / 256), 256>>>(ei32, att);
        edge_exp_kernel<<<(unsigned)((tA + 255) / 256), 256>>>(ei32);
        long long tC = (long long)ETOT * 32;
        edge_agg_kernel<<<(unsigned)((tC + 255) / 256), 256>>>(ei32);
    }

    // LN1
    ln1_kernel<<<(TNODES + 7) / 8, 256>>>(x, bias_gat, g1, be1);

    // FFN: hid = relu(h@W1 + b1); ff = hid@W2 + b2 -> out
    {
        dim3 grid1(FFD / 128, MB);
        gemm_mma<true, true><<<grid1, 256>>>(p_h, DD, W1, FFD, b1, p_hid, FFD, M, DD);
        dim3 grid2(1, MB);
        gemm_mma<false, true><<<grid2, 256>>>(p_hid, FFD, W2, DD, b2, out, DD, M, FFD);
    }

    // LN2 -> final output
    ln2_kernel<<<(TNODES + 7) / 8, 256>>>(out, g2, be2);
}

// round 6
// speedup vs baseline: 2.1705x; 1.4628x over previous
#include <cuda_runtime.h>
#include <cuda_bf16.h>
#include <math.h>
#include <stdint.h>

// ---------------- Problem constants ----------------
#define BB   8
#define TT   12
#define NN   883
#define DD   128
#define HH   8
#define CC   16
#define EE   7000
#define FFD  2048
#define NEG_SLOPE 0.2f

#define BT      (BB*TT)                 // 96
#define TNODES  (BT*NN)                 // 84768
#define ETOT    (BT*EE + TNODES)        // 756768

typedef __nv_bfloat16 bf16;
typedef __nv_bfloat162 bf162;

// ---------------- Device scratch ----------------
__device__ bf16  g_xhi[(size_t)TNODES * DD];
__device__ bf16  g_xlo[(size_t)TNODES * DD];
__device__ bf16  g_wlT_h[DD * DD];
__device__ bf16  g_wlT_l[DD * DD];
__device__ bf16  g_wrT_h[DD * DD];
__device__ bf16  g_wrT_l[DD * DD];
__device__ bf16  g_w1T_h[(size_t)FFD * DD];
__device__ bf16  g_w1T_l[(size_t)FFD * DD];
__device__ bf16  g_w2T_h[(size_t)DD * FFD];
__device__ bf16  g_w2T_l[(size_t)DD * FFD];
__device__ float g_xl[(size_t)TNODES * DD];
__device__ float g_xr[(size_t)TNODES * DD];
__device__ float g_score[(size_t)ETOT * HH];
__device__ float g_smax[(size_t)TNODES * HH];
__device__ float g_denom[(size_t)TNODES * HH];
__device__ float g_agg[(size_t)TNODES * DD];
__device__ bf16  g_hhi[(size_t)TNODES * DD];
__device__ bf16  g_hlo[(size_t)TNODES * DD];
__device__ bf16  g_hidhi[(size_t)TNODES * FFD];
__device__ bf16  g_hidlo[(size_t)TNODES * FFD];
__device__ int   g_is64;

// ---------------- Helpers ----------------
__device__ __forceinline__ uint32_t smem_to_u32(const void* p) {
    uint32_t a;
    asm("{ .reg .u64 t; cvta.to.shared.u64 t, %1; cvt.u32.u64 %0, t; }"
        : "=r"(a) : "l"(p));
    return a;
}
__device__ __forceinline__ void cp_async16(uint32_t saddr, const void* g, int src_bytes) {
    asm volatile("cp.async.cg.shared.global [%0], [%1], 16, %2;"
        :: "r"(saddr), "l"(g), "r"(src_bytes) : "memory");
}
#define CP_COMMIT() asm volatile("cp.async.commit_group;" ::: "memory")
#define CP_WAIT(N)  asm volatile("cp.async.wait_group %0;" :: "n"(N) : "memory")

__device__ __forceinline__ void ldsm_x4(uint32_t& r0, uint32_t& r1,
                                        uint32_t& r2, uint32_t& r3, uint32_t addr) {
    asm volatile("ldmatrix.sync.aligned.m8n8.x4.shared.b16 {%0,%1,%2,%3}, [%4];"
        : "=r"(r0), "=r"(r1), "=r"(r2), "=r"(r3) : "r"(addr));
}
__device__ __forceinline__ void ldsm_x2(uint32_t& r0, uint32_t& r1, uint32_t addr) {
    asm volatile("ldmatrix.sync.aligned.m8n8.x2.shared.b16 {%0,%1}, [%2];"
        : "=r"(r0), "=r"(r1) : "r"(addr));
}
__device__ __forceinline__ void mma_bf16(float* c,
                                         uint32_t a0, uint32_t a1, uint32_t a2, uint32_t a3,
                                         uint32_t b0, uint32_t b1) {
    asm volatile("mma.sync.aligned.m16n8k16.row.col.f32.bf16.bf16.f32 "
        "{%0,%1,%2,%3}, {%4,%5,%6,%7}, {%8,%9}, {%0,%1,%2,%3};"
        : "+f"(c[0]), "+f"(c[1]), "+f"(c[2]), "+f"(c[3])
        : "r"(a0), "r"(a1), "r"(a2), "r"(a3), "r"(b0), "r"(b1));
}
__device__ __forceinline__ bf16 bf_hi(float v) { return __float2bfloat16_rn(v); }

// ---------------- Pure-bf16 pipelined tensor GEMM ----------------
// C[M,N] = op(A[M,K] @ B^T)   A hi/lo: [M][K] bf16, B hi/lo: [N][K] bf16.
// grid = (N/128, ceil(M/128)), block = 256 (8 warps, warp tile 64x32)
#define SROW 40
#define TILE_E (128 * SROW)           // elems per tile
#define STAGE_E (4 * TILE_E)          // elems per stage (Ah, Al, Bh, Bl)
#define GEMM_SMEM (2 * STAGE_E * 2)   // bytes

template<bool RELU, bool SPLIT>
__global__ __launch_bounds__(256, 2)
void gemm_bf(const bf16* __restrict__ Ah, const bf16* __restrict__ Al, int lda,
             const bf16* __restrict__ Bh, const bf16* __restrict__ Bl, int ldb,
             const float* __restrict__ bias,
             float* __restrict__ C, bf16* __restrict__ Chi, bf16* __restrict__ Clo,
             int ldc, int M, int K)
{
    extern __shared__ bf16 sm[];
    const uint32_t sbase = smem_to_u32(sm);

    const int tid  = threadIdx.x;
    const int wid  = tid >> 5;
    const int lane = tid & 31;
    const int m0 = blockIdx.y * 128;
    const int n0 = blockIdx.x * 128;

    const int warp_m = (wid >> 2) * 64;
    const int warp_n = (wid & 3) * 32;

    float c[4][4][4];
    #pragma unroll
    for (int i = 0; i < 4; i++)
        #pragma unroll
        for (int j = 0; j < 4; j++)
            #pragma unroll
            for (int r = 0; r < 4; r++) c[i][j][r] = 0.0f;

    const int a_row_l = lane & 15;
    const int a_colh  = (lane >> 4) * 8;
    const int l16     = lane & 15;
    const int b_row_l = l16 & 7;
    const int b_colh  = ((l16 >> 3) & 1) * 8;

    const int nk = K >> 5;   // BK = 32

    // ---- async tile loader: 2048 16B chunks/stage, 8 per thread ----
    auto load_stage = [&](int stage, int kc) {
        const int kbase = kc << 5;
        const uint32_t sst = sbase + (uint32_t)stage * STAGE_E * 2;
        #pragma unroll
        for (int t = 0; t < 8; t++) {
            int idx  = t * 256 + tid;
            int tile = idx >> 9;           // 0..3 (uniform per t-pair)
            int rc   = idx & 511;
            int r    = rc >> 2;
            int cc   = rc & 3;
            uint32_t sa = sst + (uint32_t)(tile * TILE_E + r * SROW + cc * 8) * 2;
            const bf16* gp;
            int bytes = 16;
            if (tile < 2) {
                const bf16* base = (tile == 0) ? Ah : Al;
                int m = m0 + r;
                gp = base + (size_t)m * lda + kbase + cc * 8;
                if (m >= M) bytes = 0;
            } else {
                const bf16* base = (tile == 2) ? Bh : Bl;
                gp = base + (size_t)(n0 + r) * ldb + kbase + cc * 8;
            }
            cp_async16(sa, gp, bytes);
        }
        CP_COMMIT();
    };

    load_stage(0, 0);

    #pragma unroll 1
    for (int kc = 0; kc < nk; kc++) {
        const int cur = kc & 1;
        if (kc + 1 < nk) {
            load_stage(cur ^ 1, kc + 1);
            CP_WAIT(1);
        } else {
            CP_WAIT(0);
        }
        __syncthreads();

        const uint32_t uAh = sbase + (uint32_t)(cur * STAGE_E) * 2;
        const uint32_t uAl = uAh + TILE_E * 2;
        const uint32_t uBh = uAl + TILE_E * 2;
        const uint32_t uBl = uBh + TILE_E * 2;

        #pragma unroll
        for (int kk = 0; kk < 32; kk += 16) {
            uint32_t ah[4][4], al[4][4];
            #pragma unroll
            for (int i = 0; i < 4; i++) {
                uint32_t off = ((uint32_t)((warp_m + i * 16 + a_row_l) * SROW + a_colh + kk)) * 2;
                ldsm_x4(ah[i][0], ah[i][1], ah[i][2], ah[i][3], uAh + off);
                ldsm_x4(al[i][0], al[i][1], al[i][2], al[i][3], uAl + off);
            }
            #pragma unroll
            for (int j = 0; j < 4; j++) {
                uint32_t boff = ((uint32_t)((warp_n + j * 8 + b_row_l) * SROW + b_colh + kk)) * 2;
                uint32_t bh0, bh1, bl0, bl1;
                ldsm_x2(bh0, bh1, uBh + boff);
                ldsm_x2(bl0, bl1, uBl + boff);
                #pragma unroll
                for (int i = 0; i < 4; i++) {
                    mma_bf16(c[i][j], ah[i][0], ah[i][1], ah[i][2], ah[i][3], bh0, bh1);
                    mma_bf16(c[i][j], ah[i][0], ah[i][1], ah[i][2], ah[i][3], bl0, bl1);
                    mma_bf16(c[i][j], al[i][0], al[i][1], al[i][2], al[i][3], bh0, bh1);
                }
            }
        }
        __syncthreads();
    }

    // ---- epilogue ----
    #pragma unroll
    for (int j = 0; j < 4; j++) {
        int col = n0 + warp_n + j * 8 + (lane & 3) * 2;
        float bx = bias[col], by = bias[col + 1];
        #pragma unroll
        for (int i = 0; i < 4; i++) {
            int row = m0 + warp_m + i * 16 + (lane >> 2);
            float v0 = c[i][j][0] + bx, v1 = c[i][j][1] + by;
            float v2 = c[i][j][2] + bx, v3 = c[i][j][3] + by;
            if (RELU) {
                v0 = fmaxf(v0, 0.f); v1 = fmaxf(v1, 0.f);
                v2 = fmaxf(v2, 0.f); v3 = fmaxf(v3, 0.f);
            }
            if (SPLIT) {
                bf16 h0 = bf_hi(v0), h1 = bf_hi(v1), h2 = bf_hi(v2), h3 = bf_hi(v3);
                bf162 hi01; hi01.x = h0; hi01.y = h1;
                bf162 hi23; hi23.x = h2; hi23.y = h3;
                bf162 lo01; lo01.x = bf_hi(v0 - __bfloat162float(h0));
                            lo01.y = bf_hi(v1 - __bfloat162float(h1));
                bf162 lo23; lo23.x = bf_hi(v2 - __bfloat162float(h2));
                            lo23.y = bf_hi(v3 - __bfloat162float(h3));
                if (row < M) {
                    *(bf162*)&Chi[(size_t)row * ldc + col] = hi01;
                    *(bf162*)&Clo[(size_t)row * ldc + col] = lo01;
                }
                if (row + 8 < M) {
                    *(bf162*)&Chi[(size_t)(row + 8) * ldc + col] = hi23;
                    *(bf162*)&Clo[(size_t)(row + 8) * ldc + col] = lo23;
                }
            } else {
                if (row < M)     *(float2*)&C[(size_t)row * ldc + col]       = make_float2(v0, v1);
                if (row + 8 < M) *(float2*)&C[(size_t)(row + 8) * ldc + col] = make_float2(v2, v3);
            }
        }
    }
}

// ---------------- Operand preparation ----------------
// Row-major fp32 -> bf16 hi/lo (same layout)
__global__ void convert_split(const float* __restrict__ in,
                              bf16* __restrict__ hi, bf16* __restrict__ lo, size_t n)
{
    size_t i = ((size_t)blockIdx.x * blockDim.x + threadIdx.x) * 4;
    if (i >= n) return;
    float4 v = *(const float4*)&in[i];
    bf16 h0 = bf_hi(v.x), h1 = bf_hi(v.y), h2 = bf_hi(v.z), h3 = bf_hi(v.w);
    bf162 a; a.x = h0; a.y = h1;
    bf162 b; b.x = h2; b.y = h3;
    *(bf162*)&hi[i]     = a;
    *(bf162*)&hi[i + 2] = b;
    bf162 c; c.x = bf_hi(v.x - __bfloat162float(h0)); c.y = bf_hi(v.y - __bfloat162float(h1));
    bf162 d; d.x = bf_hi(v.z - __bfloat162float(h2)); d.y = bf_hi(v.w - __bfloat162float(h3));
    *(bf162*)&lo[i]     = c;
    *(bf162*)&lo[i + 2] = d;
}

// W [K][N] fp32 -> WT hi/lo [N][K] bf16
__global__ void transpose_split(const float* __restrict__ in,
                                bf16* __restrict__ oh, bf16* __restrict__ ol,
                                int K, int N)
{
    __shared__ float t[32][33];
    int n0 = blockIdx.x * 32, k0 = blockIdx.y * 32;
    int tx = threadIdx.x, ty = threadIdx.y;
    #pragma unroll
    for (int r = 0; r < 4; r++)
        t[ty + r * 8][tx] = in[(size_t)(k0 + ty + r * 8) * N + n0 + tx];
    __syncthreads();
    #pragma unroll
    for (int r = 0; r < 4; r++) {
        int n = n0 + ty + r * 8;
        int k = k0 + tx;
        float v = t[tx][ty + r * 8];
        bf16 h = bf_hi(v);
        oh[(size_t)n * K + k] = h;
        ol[(size_t)n * K + k] = bf_hi(v - __bfloat162float(h));
    }
}

// ---------------- Edge machinery ----------------
__device__ __forceinline__ void atomicMaxFloat(float* addr, float value) {
    if (value >= 0.0f)
        atomicMax((int*)addr, __float_as_int(value));
    else
        atomicMin((unsigned int*)addr, __float_as_uint(value));
}

__global__ void detect_kernel(const int* __restrict__ ei32) {
    if (threadIdx.x == 0 && blockIdx.x == 0) {
        int ok = 1;
        #pragma unroll
        for (int i = 1; i < 64; i += 2) ok &= (ei32[i] == 0);
        g_is64 = ok;
    }
}

__global__ void init_kernel() {
    int i = blockIdx.x * blockDim.x + threadIdx.x;
    if (i < TNODES * DD) g_agg[i] = 0.0f;
    if (i < TNODES * HH) {
        g_smax[i]  = __int_as_float(0xff800000);
        g_denom[i] = 0.0f;
    }
}

__device__ __forceinline__ int load_ei(const int* __restrict__ ei32, int is64, int idx) {
    int v = is64 ? ei32[2 * idx] : ei32[idx];
    v = v < 0 ? 0 : (v >= NN ? NN - 1 : v);
    return v;
}

__device__ __forceinline__ void edge_decode(int e, const int* __restrict__ ei32,
                                            int is64, int& src, int& dst)
{
    if (e < BT * EE) {
        int inst = e / EE;
        int idx  = e - inst * EE;
        int base = inst * NN;
        src = load_ei(ei32, is64, idx) + base;
        dst = load_ei(ei32, is64, EE + idx) + base;
    } else {
        src = dst = e - BT * EE;
    }
}

__global__ void edge_score_kernel(const int* __restrict__ ei32,
                                  const float* __restrict__ att)
{
    int t = blockIdx.x * blockDim.x + threadIdx.x;
    if (t >= ETOT * HH) return;
    int e = t >> 3;
    int h = t & 7;
    int is64 = g_is64;
    int src, dst;
    edge_decode(e, ei32, is64, src, dst);

    const float4* xl = (const float4*)&g_xl[(size_t)src * DD + h * CC];
    const float4* xr = (const float4*)&g_xr[(size_t)dst * DD + h * CC];
    const float4* at = (const float4*)&att[h * CC];

    float s = 0.0f;
    #pragma unroll
    for (int q = 0; q < 4; q++) {
        float4 a = xl[q];
        float4 b = xr[q];
        float4 w = at[q];
        float v0 = a.x + b.x; v0 = v0 > 0.f ? v0 : NEG_SLOPE * v0;
        float v1 = a.y + b.y; v1 = v1 > 0.f ? v1 : NEG_SLOPE * v1;
        float v2 = a.z + b.z; v2 = v2 > 0.f ? v2 : NEG_SLOPE * v2;
        float v3 = a.w + b.w; v3 = v3 > 0.f ? v3 : NEG_SLOPE * v3;
        s = fmaf(w.x, v0, s);
        s = fmaf(w.y, v1, s);
        s = fmaf(w.z, v2, s);
        s = fmaf(w.w, v3, s);
    }
    g_score[t] = s;
    atomicMaxFloat(&g_smax[(size_t)dst * HH + h], s);
}

__global__ void edge_exp_kernel(const int* __restrict__ ei32)
{
    int t = blockIdx.x * blockDim.x + threadIdx.x;
    if (t >= ETOT * HH) return;
    int e = t >> 3;
    int h = t & 7;
    int is64 = g_is64;
    int src, dst;
    edge_decode(e, ei32, is64, src, dst);
    float a = expf(g_score[t] - g_smax[(size_t)dst * HH + h]);
    g_score[t] = a;
    atomicAdd(&g_denom[(size_t)dst * HH + h], a);
}

__global__ void edge_agg_kernel(const int* __restrict__ ei32)
{
    long long t = (long long)blockIdx.x * blockDim.x + threadIdx.x;
    if (t >= (long long)ETOT * 32) return;
    int e = (int)(t >> 5);
    int r = (int)(t & 31);
    int h = r >> 2;
    int q = r & 3;
    int is64 = g_is64;
    int src, dst;
    edge_decode(e, ei32, is64, src, dst);
    float alpha = g_score[(size_t)e * HH + h] / g_denom[(size_t)dst * HH + h];
    float4 xlv = *(const float4*)&g_xl[(size_t)src * DD + h * CC + q * 4];
    float* out = &g_agg[(size_t)dst * DD + h * CC + q * 4];
    atomicAdd(out + 0, alpha * xlv.x);
    atomicAdd(out + 1, alpha * xlv.y);
    atomicAdd(out + 2, alpha * xlv.z);
    atomicAdd(out + 3, alpha * xlv.w);
}

// ---------------- LayerNorms ----------------
// LN1: h = LN(x + agg + bias_gat) -> split bf16 (g_hhi/g_hlo)
__global__ void ln1_kernel(const float* __restrict__ x,
                           const float* __restrict__ bias_gat,
                           const float* __restrict__ g,
                           const float* __restrict__ b)
{
    int row = blockIdx.x * 8 + (threadIdx.x >> 5);
    if (row >= TNODES) return;
    int lane = threadIdx.x & 31;
    size_t base = (size_t)row * DD + lane * 4;

    float4 xv = *(const float4*)&x[base];
    float4 av = *(const float4*)&g_agg[base];
    float4 bg = *(const float4*)&bias_gat[lane * 4];
    float v[4] = {xv.x + av.x + bg.x, xv.y + av.y + bg.y,
                  xv.z + av.z + bg.z, xv.w + av.w + bg.w};

    float s = v[0] + v[1] + v[2] + v[3];
    #pragma unroll
    for (int o = 16; o > 0; o >>= 1) s += __shfl_xor_sync(0xffffffffu, s, o);
    float mu = s * (1.0f / DD);

    float sq = 0.f;
    #pragma unroll
    for (int i = 0; i < 4; i++) { float d = v[i] - mu; sq += d * d; }
    #pragma unroll
    for (int o = 16; o > 0; o >>= 1) sq += __shfl_xor_sync(0xffffffffu, sq, o);
    float rstd = rsqrtf(sq * (1.0f / DD) + 1e-5f);

    float4 gv = *(const float4*)&g[lane * 4];
    float4 bv = *(const float4*)&b[lane * 4];
    float h0 = (v[0] - mu) * rstd * gv.x + bv.x;
    float h1 = (v[1] - mu) * rstd * gv.y + bv.y;
    float h2 = (v[2] - mu) * rstd * gv.z + bv.z;
    float h3 = (v[3] - mu) * rstd * gv.w + bv.w;

    bf16 a0 = bf_hi(h0), a1 = bf_hi(h1), a2 = bf_hi(h2), a3 = bf_hi(h3);
    bf162 hi01; hi01.x = a0; hi01.y = a1;
    bf162 hi23; hi23.x = a2; hi23.y = a3;
    bf162 lo01; lo01.x = bf_hi(h0 - __bfloat162float(a0));
                lo01.y = bf_hi(h1 - __bfloat162float(a1));
    bf162 lo23; lo23.x = bf_hi(h2 - __bfloat162float(a2));
                lo23.y = bf_hi(h3 - __bfloat162float(a3));
    *(bf162*)&g_hhi[base]     = hi01;
    *(bf162*)&g_hhi[base + 2] = hi23;
    *(bf162*)&g_hlo[base]     = lo01;
    *(bf162*)&g_hlo[base + 2] = lo23;
}

// LN2: out = LN((hhi+hlo) + ff), ff staged in d_out
__global__ void ln2_kernel(float* __restrict__ out,
                           const float* __restrict__ g,
                           const float* __restrict__ b)
{
    int row = blockIdx.x * 8 + (threadIdx.x >> 5);
    if (row >= TNODES) return;
    int lane = threadIdx.x & 31;
    size_t base = (size_t)row * DD + lane * 4;

    bf162 h01 = *(const bf162*)&g_hhi[base];
    bf162 h23 = *(const bf162*)&g_hhi[base + 2];
    bf162 l01 = *(const bf162*)&g_hlo[base];
    bf162 l23 = *(const bf162*)&g_hlo[base + 2];
    float4 fv = *(const float4*)&out[base];
    float v[4];
    v[0] = __bfloat162float(h01.x) + __bfloat162float(l01.x) + fv.x;
    v[1] = __bfloat162float(h01.y) + __bfloat162float(l01.y) + fv.y;
    v[2] = __bfloat162float(h23.x) + __bfloat162float(l23.x) + fv.z;
    v[3] = __bfloat162float(h23.y) + __bfloat162float(l23.y) + fv.w;

    float s = v[0] + v[1] + v[2] + v[3];
    #pragma unroll
    for (int o = 16; o > 0; o >>= 1) s += __shfl_xor_sync(0xffffffffu, s, o);
    float mu = s * (1.0f / DD);

    float sq = 0.f;
    #pragma unroll
    for (int i = 0; i < 4; i++) { float d = v[i] - mu; sq += d * d; }
    #pragma unroll
    for (int o = 16; o > 0; o >>= 1) sq += __shfl_xor_sync(0xffffffffu, sq, o);
    float rstd = rsqrtf(sq * (1.0f / DD) + 1e-5f);

    float4 gv = *(const float4*)&g[lane * 4];
    float4 bv = *(const float4*)&b[lane * 4];
    float4 o4;
    o4.x = (v[0] - mu) * rstd * gv.x + bv.x;
    o4.y = (v[1] - mu) * rstd * gv.y + bv.y;
    o4.z = (v[2] - mu) * rstd * gv.z + bv.z;
    o4.w = (v[3] - mu) * rstd * gv.w + bv.w;
    *(float4*)&out[base] = o4;
}

// ---------------- Launch ----------------
extern "C" void kernel_launch(void* const* d_in, const int* in_sizes, int n_in,
                              void* d_out, int out_size)
{
    const float* x        = (const float*)d_in[0];
    const int*   ei32     = (const int*)d_in[1];
    const float* Wl       = (const float*)d_in[2];
    const float* bl       = (const float*)d_in[3];
    const float* Wr       = (const float*)d_in[4];
    const float* br       = (const float*)d_in[5];
    const float* att      = (const float*)d_in[6];
    const float* bias_gat = (const float*)d_in[7];
    const float* W1       = (const float*)d_in[8];
    const float* b1       = (const float*)d_in[9];
    const float* W2       = (const float*)d_in[10];
    const float* b2       = (const float*)d_in[11];
    const float* g1       = (const float*)d_in[12];
    const float* be1      = (const float*)d_in[13];
    const float* g2       = (const float*)d_in[14];
    const float* be2      = (const float*)d_in[15];
    float*       out      = (float*)d_out;

    bf16 *p_xhi, *p_xlo, *p_wlh, *p_wll, *p_wrh, *p_wrl;
    bf16 *p_w1h, *p_w1l, *p_w2h, *p_w2l;
    bf16 *p_hhi, *p_hlo, *p_hidh, *p_hidl;
    float *p_xl, *p_xr;
    cudaGetSymbolAddress((void**)&p_xhi,  g_xhi);
    cudaGetSymbolAddress((void**)&p_xlo,  g_xlo);
    cudaGetSymbolAddress((void**)&p_wlh,  g_wlT_h);
    cudaGetSymbolAddress((void**)&p_wll,  g_wlT_l);
    cudaGetSymbolAddress((void**)&p_wrh,  g_wrT_h);
    cudaGetSymbolAddress((void**)&p_wrl,  g_wrT_l);
    cudaGetSymbolAddress((void**)&p_w1h,  g_w1T_h);
    cudaGetSymbolAddress((void**)&p_w1l,  g_w1T_l);
    cudaGetSymbolAddress((void**)&p_w2h,  g_w2T_h);
    cudaGetSymbolAddress((void**)&p_w2l,  g_w2T_l);
    cudaGetSymbolAddress((void**)&p_hhi,  g_hhi);
    cudaGetSymbolAddress((void**)&p_hlo,  g_hlo);
    cudaGetSymbolAddress((void**)&p_hidh, g_hidhi);
    cudaGetSymbolAddress((void**)&p_hidl, g_hidlo);
    cudaGetSymbolAddress((void**)&p_xl,   g_xl);
    cudaGetSymbolAddress((void**)&p_xr,   g_xr);

    cudaFuncSetAttribute(gemm_bf<false, false>,
                         cudaFuncAttributeMaxDynamicSharedMemorySize, GEMM_SMEM);
    cudaFuncSetAttribute(gemm_bf<true, true>,
                         cudaFuncAttributeMaxDynamicSharedMemorySize, GEMM_SMEM);

    const int M  = TNODES;
    const int MB = (M + 127) / 128;   // 663

    detect_kernel<<<1, 32>>>(ei32);
    {
        int n = TNODES * DD;
        init_kernel<<<(n + 255) / 256, 256>>>();
    }

    // Operand prep
    {
        size_t n = (size_t)TNODES * DD;
        convert_split<<<(unsigned)((n / 4 + 255) / 256), 256>>>(x, p_xhi, p_xlo, n);
        dim3 blk(32, 8);
        transpose_split<<<dim3(4, 4),   blk>>>(Wl, p_wlh, p_wll, DD, DD);
        transpose_split<<<dim3(4, 4),   blk>>>(Wr, p_wrh, p_wrl, DD, DD);
        transpose_split<<<dim3(64, 4),  blk>>>(W1, p_w1h, p_w1l, DD, FFD);
        transpose_split<<<dim3(4, 64),  blk>>>(W2, p_w2h, p_w2l, FFD, DD);
    }

    // projections
    {
        dim3 grid(1, MB);
        gemm_bf<false, false><<<grid, 256, GEMM_SMEM>>>(
            p_xhi, p_xlo, DD, p_wlh, p_wll, DD, bl, p_xl, nullptr, nullptr, DD, M, DD);
        gemm_bf<false, false><<<grid, 256, GEMM_SMEM>>>(
            p_xhi, p_xlo, DD, p_wrh, p_wrl, DD, br, p_xr, nullptr, nullptr, DD, M, DD);
    }

    // edge passes
    {
        long long tA = (long long)ETOT * HH;
        edge_score_kernel<<<(unsigned)((tA + 255) / 256), 256>>>(ei32, att);
        edge_exp_kernel<<<(unsigned)((tA + 255) / 256), 256>>>(ei32);
        long long tC = (long long)ETOT * 32;
        edge_agg_kernel<<<(unsigned)((tC + 255) / 256), 256>>>(ei32);
    }

    // LN1 -> split h
    ln1_kernel<<<(TNODES + 7) / 8, 256>>>(x, bias_gat, g1, be1);

    // FFN
    {
        dim3 grid1(FFD / 128, MB);
        gemm_bf<true, true><<<grid1, 256, GEMM_SMEM>>>(
            p_hhi, p_hlo, DD, p_w1h, p_w1l, DD, b1,
            nullptr, p_hidh, p_hidl, FFD, M, DD);
        dim3 grid2(1, MB);
        gemm_bf<false, false><<<grid2, 256, GEMM_SMEM>>>(
            p_hidh, p_hidl, FFD, p_w2h, p_w2l, FFD, b2,
            out, nullptr, nullptr, DD, M, FFD);
    }

    // LN2 -> final output
    ln2_kernel<<<(TNODES + 7) / 8, 256>>>(out, g2, be2);
}

// round 8
// speedup vs baseline: 2.4828x; 1.1439x over previous
#include <cuda_runtime.h>
#include <cuda_bf16.h>
#include <math.h>
#include <stdint.h>

// ---------------- Problem constants ----------------
#define BB   8
#define TT   12
#define NN   883
#define DD   128
#define HH   8
#define CC   16
#define EE   7000
#define FFD  2048
#define NEG_SLOPE 0.2f

#define BT      (BB*TT)                 // 96
#define TNODES  (BT*NN)                 // 84768
#define MAXDEG  256

typedef __nv_bfloat16 bf16;
typedef __nv_bfloat162 bf162;

// ---------------- Device scratch ----------------
__device__ bf16  g_xhi[(size_t)TNODES * DD];
__device__ bf16  g_xlo[(size_t)TNODES * DD];
__device__ bf16  g_wcT_h[2 * DD * DD];            // [Wl^T ; Wr^T]  256 x 128
__device__ bf16  g_wcT_l[2 * DD * DD];
__device__ bf16  g_w1T_h[(size_t)FFD * DD];
__device__ bf16  g_w1T_l[(size_t)FFD * DD];
__device__ bf16  g_w2T_h[(size_t)DD * FFD];
__device__ bf16  g_w2T_l[(size_t)DD * FFD];
__device__ float g_xl[(size_t)TNODES * DD];
__device__ float g_xr[(size_t)TNODES * DD];
__device__ bf16  g_hhi[(size_t)TNODES * DD];
__device__ bf16  g_hlo[(size_t)TNODES * DD];
__device__ bf16  g_hidhi[(size_t)TNODES * FFD];
__device__ bf16  g_hidlo[(size_t)TNODES * FFD];
__device__ int   g_is64;
// CSR of the shared base graph (883 nodes, 7000 edges + self-loops)
__device__ int   g_deg[NN];
__device__ int   g_rowptr[NN + 1];
__device__ int   g_ecnt[NN];
__device__ int   g_esrc[EE + NN];

// ---------------- Helpers ----------------
__device__ __forceinline__ uint32_t smem_to_u32(const void* p) {
    uint32_t a;
    asm("{ .reg .u64 t; cvta.to.shared.u64 t, %1; cvt.u32.u64 %0, t; }"
        : "=r"(a) : "l"(p));
    return a;
}
__device__ __forceinline__ void cp_async16(uint32_t saddr, const void* g, int src_bytes) {
    asm volatile("cp.async.cg.shared.global [%0], [%1], 16, %2;"
        :: "r"(saddr), "l"(g), "r"(src_bytes) : "memory");
}
#define CP_COMMIT() asm volatile("cp.async.commit_group;" ::: "memory")
#define CP_WAIT(N)  asm volatile("cp.async.wait_group %0;" :: "n"(N) : "memory")

__device__ __forceinline__ void ldsm_x4(uint32_t& r0, uint32_t& r1,
                                        uint32_t& r2, uint32_t& r3, uint32_t addr) {
    asm volatile("ldmatrix.sync.aligned.m8n8.x4.shared.b16 {%0,%1,%2,%3}, [%4];"
        : "=r"(r0), "=r"(r1), "=r"(r2), "=r"(r3) : "r"(addr));
}
__device__ __forceinline__ void ldsm_x2(uint32_t& r0, uint32_t& r1, uint32_t addr) {
    asm volatile("ldmatrix.sync.aligned.m8n8.x2.shared.b16 {%0,%1}, [%2];"
        : "=r"(r0), "=r"(r1) : "r"(addr));
}
__device__ __forceinline__ void mma_bf16(float* c,
                                         uint32_t a0, uint32_t a1, uint32_t a2, uint32_t a3,
                                         uint32_t b0, uint32_t b1) {
    asm volatile("mma.sync.aligned.m16n8k16.row.col.f32.bf16.bf16.f32 "
        "{%0,%1,%2,%3}, {%4,%5,%6,%7}, {%8,%9}, {%0,%1,%2,%3};"
        : "+f"(c[0]), "+f"(c[1]), "+f"(c[2]), "+f"(c[3])
        : "r"(a0), "r"(a1), "r"(a2), "r"(a3), "r"(b0), "r"(b1));
}
__device__ __forceinline__ bf16 bf_hi(float v) { return __float2bfloat16_rn(v); }

// ---------------- Pure-bf16 pipelined tensor GEMM ----------------
// MODE 0: C = A@B^T + bias (fp32 out)
// MODE 1: relu(A@B^T + bias) -> split bf16 (Chi/Clo)
// MODE 2: projection dual: cols [0,128) -> C (+bias), cols [128,256) -> C2 (+bias2)
#define SROW 40
#define TILE_E (128 * SROW)
#define STAGE_E (4 * TILE_E)
#define GEMM_SMEM (2 * STAGE_E * 2)

template<int MODE>
__global__ __launch_bounds__(256, 2)
void gemm_bf(const bf16* __restrict__ Ah, const bf16* __restrict__ Al, int lda,
             const bf16* __restrict__ Bh, const bf16* __restrict__ Bl, int ldb,
             const float* __restrict__ bias, const float* __restrict__ bias2,
             float* __restrict__ C, float* __restrict__ C2,
             bf16* __restrict__ Chi, bf16* __restrict__ Clo,
             int ldc, int M, int K)
{
    extern __shared__ bf16 sm[];
    const uint32_t sbase = smem_to_u32(sm);

    const int tid  = threadIdx.x;
    const int wid  = tid >> 5;
    const int lane = tid & 31;
    const int m0 = blockIdx.y * 128;
    const int n0 = blockIdx.x * 128;

    const int warp_m = (wid >> 2) * 64;
    const int warp_n = (wid & 3) * 32;

    float c[4][4][4];
    #pragma unroll
    for (int i = 0; i < 4; i++)
        #pragma unroll
        for (int j = 0; j < 4; j++)
            #pragma unroll
            for (int r = 0; r < 4; r++) c[i][j][r] = 0.0f;

    const int a_row_l = lane & 15;
    const int a_colh  = (lane >> 4) * 8;
    const int l16     = lane & 15;
    const int b_row_l = l16 & 7;
    const int b_colh  = ((l16 >> 3) & 1) * 8;

    const int nk = K >> 5;

    auto load_stage = [&](int stage, int kc) {
        const int kbase = kc << 5;
        const uint32_t sst = sbase + (uint32_t)stage * STAGE_E * 2;
        #pragma unroll
        for (int t = 0; t < 8; t++) {
            int idx  = t * 256 + tid;
            int tile = idx >> 9;
            int rc   = idx & 511;
            int r    = rc >> 2;
            int cc   = rc & 3;
            uint32_t sa = sst + (uint32_t)(tile * TILE_E + r * SROW + cc * 8) * 2;
            const bf16* gp;
            int bytes = 16;
            if (tile < 2) {
                const bf16* base = (tile == 0) ? Ah : Al;
                int m = m0 + r;
                gp = base + (size_t)m * lda + kbase + cc * 8;
                if (m >= M) bytes = 0;
            } else {
                const bf16* base = (tile == 2) ? Bh : Bl;
                gp = base + (size_t)(n0 + r) * ldb + kbase + cc * 8;
            }
            cp_async16(sa, gp, bytes);
        }
        CP_COMMIT();
    };

    load_stage(0, 0);

    #pragma unroll 1
    for (int kc = 0; kc < nk; kc++) {
        const int cur = kc & 1;
        if (kc + 1 < nk) {
            load_stage(cur ^ 1, kc + 1);
            CP_WAIT(1);
        } else {
            CP_WAIT(0);
        }
        __syncthreads();

        const uint32_t uAh = sbase + (uint32_t)(cur * STAGE_E) * 2;
        const uint32_t uAl = uAh + TILE_E * 2;
        const uint32_t uBh = uAl + TILE_E * 2;
        const uint32_t uBl = uBh + TILE_E * 2;

        #pragma unroll
        for (int kk = 0; kk < 32; kk += 16) {
            uint32_t ah[4][4], al[4][4];
            #pragma unroll
            for (int i = 0; i < 4; i++) {
                uint32_t off = ((uint32_t)((warp_m + i * 16 + a_row_l) * SROW + a_colh + kk)) * 2;
                ldsm_x4(ah[i][0], ah[i][1], ah[i][2], ah[i][3], uAh + off);
                ldsm_x4(al[i][0], al[i][1], al[i][2], al[i][3], uAl + off);
            }
            #pragma unroll
            for (int j = 0; j < 4; j++) {
                uint32_t boff = ((uint32_t)((warp_n + j * 8 + b_row_l) * SROW + b_colh + kk)) * 2;
                uint32_t bh0, bh1, bl0, bl1;
                ldsm_x2(bh0, bh1, uBh + boff);
                ldsm_x2(bl0, bl1, uBl + boff);
                #pragma unroll
                for (int i = 0; i < 4; i++) {
                    mma_bf16(c[i][j], ah[i][0], ah[i][1], ah[i][2], ah[i][3], bh0, bh1);
                    mma_bf16(c[i][j], ah[i][0], ah[i][1], ah[i][2], ah[i][3], bl0, bl1);
                    mma_bf16(c[i][j], al[i][0], al[i][1], al[i][2], al[i][3], bh0, bh1);
                }
            }
        }
        __syncthreads();
    }

    // ---- epilogue ----
    #pragma unroll
    for (int j = 0; j < 4; j++) {
        int colg = n0 + warp_n + j * 8 + (lane & 3) * 2;
        float*       Cp = C;
        const float* bp = bias;
        int col = colg;
        if (MODE == 2 && colg >= 128) { Cp = C2; bp = bias2; col = colg - 128; }
        float bx = bp[col], by = bp[col + 1];
        #pragma unroll
        for (int i = 0; i < 4; i++) {
            int row = m0 + warp_m + i * 16 + (lane >> 2);
            float v0 = c[i][j][0] + bx, v1 = c[i][j][1] + by;
            float v2 = c[i][j][2] + bx, v3 = c[i][j][3] + by;
            if (MODE == 1) {
                v0 = fmaxf(v0, 0.f); v1 = fmaxf(v1, 0.f);
                v2 = fmaxf(v2, 0.f); v3 = fmaxf(v3, 0.f);
                bf16 h0 = bf_hi(v0), h1 = bf_hi(v1), h2 = bf_hi(v2), h3 = bf_hi(v3);
                bf162 hi01; hi01.x = h0; hi01.y = h1;
                bf162 hi23; hi23.x = h2; hi23.y = h3;
                bf162 lo01; lo01.x = bf_hi(v0 - __bfloat162float(h0));
                            lo01.y = bf_hi(v1 - __bfloat162float(h1));
                bf162 lo23; lo23.x = bf_hi(v2 - __bfloat162float(h2));
                            lo23.y = bf_hi(v3 - __bfloat162float(h3));
                if (row < M) {
                    *(bf162*)&Chi[(size_t)row * ldc + col] = hi01;
                    *(bf162*)&Clo[(size_t)row * ldc + col] = lo01;
                }
                if (row + 8 < M) {
                    *(bf162*)&Chi[(size_t)(row + 8) * ldc + col] = hi23;
                    *(bf162*)&Clo[(size_t)(row + 8) * ldc + col] = lo23;
                }
            } else {
                int ld = (MODE == 2) ? DD : ldc;
                if (row < M)     *(float2*)&Cp[(size_t)row * ld + col]       = make_float2(v0, v1);
                if (row + 8 < M) *(float2*)&Cp[(size_t)(row + 8) * ld + col] = make_float2(v2, v3);
            }
        }
    }
}

// ---------------- Operand preparation ----------------
__global__ void convert_split(const float* __restrict__ in,
                              bf16* __restrict__ hi, bf16* __restrict__ lo, size_t n)
{
    size_t i = ((size_t)blockIdx.x * blockDim.x + threadIdx.x) * 4;
    if (i >= n) return;
    float4 v = *(const float4*)&in[i];
    bf16 h0 = bf_hi(v.x), h1 = bf_hi(v.y), h2 = bf_hi(v.z), h3 = bf_hi(v.w);
    bf162 a; a.x = h0; a.y = h1;
    bf162 b; b.x = h2; b.y = h3;
    *(bf162*)&hi[i]     = a;
    *(bf162*)&hi[i + 2] = b;
    bf162 c; c.x = bf_hi(v.x - __bfloat162float(h0)); c.y = bf_hi(v.y - __bfloat162float(h1));
    bf162 d; d.x = bf_hi(v.z - __bfloat162float(h2)); d.y = bf_hi(v.w - __bfloat162float(h3));
    *(bf162*)&lo[i]     = c;
    *(bf162*)&lo[i + 2] = d;
}

__global__ void transpose_split(const float* __restrict__ in,
                                bf16* __restrict__ oh, bf16* __restrict__ ol,
                                int K, int N)
{
    __shared__ float t[32][33];
    int n0 = blockIdx.x * 32, k0 = blockIdx.y * 32;
    int tx = threadIdx.x, ty = threadIdx.y;
    #pragma unroll
    for (int r = 0; r < 4; r++)
        t[ty + r * 8][tx] = in[(size_t)(k0 + ty + r * 8) * N + n0 + tx];
    __syncthreads();
    #pragma unroll
    for (int r = 0; r < 4; r++) {
        int n = n0 + ty + r * 8;
        int k = k0 + tx;
        float v = t[tx][ty + r * 8];
        bf16 h = bf_hi(v);
        oh[(size_t)n * K + k] = h;
        ol[(size_t)n * K + k] = bf_hi(v - __bfloat162float(h));
    }
}

// ---------------- Edge decode + CSR build ----------------
__global__ void detect_kernel(const int* __restrict__ ei32) {
    if (threadIdx.x == 0 && blockIdx.x == 0) {
        int ok = 1;
        #pragma unroll
        for (int i = 1; i < 64; i += 2) ok &= (ei32[i] == 0);
        g_is64 = ok;
    }
}
__device__ __forceinline__ int load_ei(const int* __restrict__ ei32, int is64, int idx) {
    int v = is64 ? ei32[2 * idx] : ei32[idx];
    v = v < 0 ? 0 : (v >= NN ? NN - 1 : v);
    return v;
}

__global__ void csr_zero() {
    int t = blockIdx.x * blockDim.x + threadIdx.x;
    if (t < NN) { g_deg[t] = 1; g_ecnt[t] = 0; }   // deg starts at 1 (self-loop)
}
__global__ void csr_hist(const int* __restrict__ ei32) {
    int i = blockIdx.x * blockDim.x + threadIdx.x;
    if (i >= EE) return;
    int dst = load_ei(ei32, g_is64, EE + i);
    atomicAdd(&g_deg[dst], 1);
}
__global__ void csr_scan() {
    __shared__ int tmp[1024];
    int t = threadIdx.x;
    tmp[t] = (t < NN) ? g_deg[t] : 0;
    __syncthreads();
    #pragma unroll
    for (int o = 1; o < 1024; o <<= 1) {
        int u = (t >= o) ? tmp[t - o] : 0;
        __syncthreads();
        tmp[t] += u;
        __syncthreads();
    }
    if (t < NN) g_rowptr[t + 1] = tmp[t];
    if (t == 0) g_rowptr[0] = 0;
}
__global__ void csr_fill(const int* __restrict__ ei32) {
    int i = blockIdx.x * blockDim.x + threadIdx.x;
    if (i >= EE + NN) return;
    int src, dst;
    if (i < EE) {
        src = load_ei(ei32, g_is64, i);
        dst = load_ei(ei32, g_is64, EE + i);
    } else {
        src = dst = i - EE;
    }
    int pos = g_rowptr[dst] + atomicAdd(&g_ecnt[dst], 1);
    g_esrc[pos] = src;
}

// ---------------- Fused GAT softmax+aggregate+LN1 ----------------
// 1 block = 1 node (128 threads, thread t = channel t, head = t/16)
__global__ __launch_bounds__(128)
void gat_fused_kernel(const float* __restrict__ att,
                      const float* __restrict__ x,
                      const float* __restrict__ bias_gat,
                      const float* __restrict__ g1,
                      const float* __restrict__ be1)
{
    __shared__ float sc[MAXDEG * 8];
    __shared__ float red1[4], red2[4];

    const int node = blockIdx.x;
    const int t    = threadIdx.x;
    const int h    = t >> 4;
    const int cch  = t & 15;
    const int wid  = t >> 5;
    const int lane = t & 31;

    const int inst  = node / NN;
    const int local = node - inst * NN;
    const int ibase = inst * NN;
    const int rs    = g_rowptr[local];
    int deg = g_rowptr[local + 1] - rs;
    if (deg > MAXDEG) deg = MAXDEG;

    const float xr = g_xr[(size_t)node * DD + t];
    const float at = att[t];

    // pass 1: scores + per-head max
    float m = -INFINITY;
    for (int e = 0; e < deg; e++) {
        int src = ibase + g_esrc[rs + e];
        float xl = g_xl[(size_t)src * DD + t];
        float v = xl + xr;
        v = v > 0.f ? v : NEG_SLOPE * v;
        float p = at * v;
        #pragma unroll
        for (int o = 8; o > 0; o >>= 1) p += __shfl_xor_sync(0xffffffffu, p, o, 16);
        if (cch == 0) sc[e * 8 + h] = p;
        m = fmaxf(m, p);
    }
    __syncwarp();

    // pass 2: exp + denom (store exp back to smem)
    float s = 0.f;
    for (int e = 0; e < deg; e++) {
        float a = expf(sc[e * 8 + h] - m);
        s += a;
        __syncwarp();
        if (cch == 0) sc[e * 8 + h] = a;
        __syncwarp();
    }
    float inv_s = 1.0f / s;

    // pass 3: aggregate
    float agg = 0.f;
    for (int e = 0; e < deg; e++) {
        int src = ibase + g_esrc[rs + e];
        float xl = g_xl[(size_t)src * DD + t];
        agg = fmaf(sc[e * 8 + h] * inv_s, xl, agg);
    }

    // LN1: v = x + agg + bias_gat, normalize over 128
    float v = x[(size_t)node * DD + t] + agg + bias_gat[t];
    float sum = v;
    #pragma unroll
    for (int o = 16; o > 0; o >>= 1) sum += __shfl_xor_sync(0xffffffffu, sum, o);
    if (lane == 0) red1[wid] = sum;
    __syncthreads();
    sum = red1[0] + red1[1] + red1[2] + red1[3];
    float mu = sum * (1.0f / DD);

    float d = v - mu;
    float sq = d * d;
    #pragma unroll
    for (int o = 16; o > 0; o >>= 1) sq += __shfl_xor_sync(0xffffffffu, sq, o);
    if (lane == 0) red2[wid] = sq;
    __syncthreads();
    sq = red2[0] + red2[1] + red2[2] + red2[3];
    float rstd = rsqrtf(sq * (1.0f / DD) + 1e-5f);

    float hv = d * rstd * g1[t] + be1[t];
    bf16 hh = bf_hi(hv);
    g_hhi[(size_t)node * DD + t] = hh;
    g_hlo[(size_t)node * DD + t] = bf_hi(hv - __bfloat162float(hh));
}

// ---------------- LN2: out = LN((hhi+hlo) + ff), ff staged in d_out ----------------
__global__ void ln2_kernel(float* __restrict__ out,
                           const float* __restrict__ g,
                           const float* __restrict__ b)
{
    int row = blockIdx.x * 8 + (threadIdx.x >> 5);
    if (row >= TNODES) return;
    int lane = threadIdx.x & 31;
    size_t base = (size_t)row * DD + lane * 4;

    bf162 h01 = *(const bf162*)&g_hhi[base];
    bf162 h23 = *(const bf162*)&g_hhi[base + 2];
    bf162 l01 = *(const bf162*)&g_hlo[base];
    bf162 l23 = *(const bf162*)&g_hlo[base + 2];
    float4 fv = *(const float4*)&out[base];
    float v[4];
    v[0] = __bfloat162float(h01.x) + __bfloat162float(l01.x) + fv.x;
    v[1] = __bfloat162float(h01.y) + __bfloat162float(l01.y) + fv.y;
    v[2] = __bfloat162float(h23.x) + __bfloat162float(l23.x) + fv.z;
    v[3] = __bfloat162float(h23.y) + __bfloat162float(l23.y) + fv.w;

    float s = v[0] + v[1] + v[2] + v[3];
    #pragma unroll
    for (int o = 16; o > 0; o >>= 1) s += __shfl_xor_sync(0xffffffffu, s, o);
    float mu = s * (1.0f / DD);

    float sq = 0.f;
    #pragma unroll
    for (int i = 0; i < 4; i++) { float d = v[i] - mu; sq += d * d; }
    #pragma unroll
    for (int o = 16; o > 0; o >>= 1) sq += __shfl_xor_sync(0xffffffffu, sq, o);
    float rstd = rsqrtf(sq * (1.0f / DD) + 1e-5f);

    float4 gv = *(const float4*)&g[lane * 4];
    float4 bv = *(const float4*)&b[lane * 4];
    float4 o4;
    o4.x = (v[0] - mu) * rstd * gv.x + bv.x;
    o4.y = (v[1] - mu) * rstd * gv.y + bv.y;
    o4.z = (v[2] - mu) * rstd * gv.z + bv.z;
    o4.w = (v[3] - mu) * rstd * gv.w + bv.w;
    *(float4*)&out[base] = o4;
}

// ---------------- Launch ----------------
extern "C" void kernel_launch(void* const* d_in, const int* in_sizes, int n_in,
                              void* d_out, int out_size)
{
    const float* x        = (const float*)d_in[0];
    const int*   ei32     = (const int*)d_in[1];
    const float* Wl       = (const float*)d_in[2];
    const float* bl       = (const float*)d_in[3];
    const float* Wr       = (const float*)d_in[4];
    const float* br       = (const float*)d_in[5];
    const float* att      = (const float*)d_in[6];
    const float* bias_gat = (const float*)d_in[7];
    const float* W1       = (const float*)d_in[8];
    const float* b1       = (const float*)d_in[9];
    const float* W2       = (const float*)d_in[10];
    const float* b2       = (const float*)d_in[11];
    const float* g1       = (const float*)d_in[12];
    const float* be1      = (const float*)d_in[13];
    const float* g2       = (const float*)d_in[14];
    const float* be2      = (const float*)d_in[15];
    float*       out      = (float*)d_out;

    bf16 *p_xhi, *p_xlo, *p_wch, *p_wcl, *p_w1h, *p_w1l, *p_w2h, *p_w2l;
    bf16 *p_hhi, *p_hlo, *p_hidh, *p_hidl;
    float *p_xl, *p_xr;
    cudaGetSymbolAddress((void**)&p_xhi,  g_xhi);
    cudaGetSymbolAddress((void**)&p_xlo,  g_xlo);
    cudaGetSymbolAddress((void**)&p_wch,  g_wcT_h);
    cudaGetSymbolAddress((void**)&p_wcl,  g_wcT_l);
    cudaGetSymbolAddress((void**)&p_w1h,  g_w1T_h);
    cudaGetSymbolAddress((void**)&p_w1l,  g_w1T_l);
    cudaGetSymbolAddress((void**)&p_w2h,  g_w2T_h);
    cudaGetSymbolAddress((void**)&p_w2l,  g_w2T_l);
    cudaGetSymbolAddress((void**)&p_hhi,  g_hhi);
    cudaGetSymbolAddress((void**)&p_hlo,  g_hlo);
    cudaGetSymbolAddress((void**)&p_hidh, g_hidhi);
    cudaGetSymbolAddress((void**)&p_hidl, g_hidlo);
    cudaGetSymbolAddress((void**)&p_xl,   g_xl);
    cudaGetSymbolAddress((void**)&p_xr,   g_xr);

    cudaFuncSetAttribute(gemm_bf<0>, cudaFuncAttributeMaxDynamicSharedMemorySize, GEMM_SMEM);
    cudaFuncSetAttribute(gemm_bf<1>, cudaFuncAttributeMaxDynamicSharedMemorySize, GEMM_SMEM);
    cudaFuncSetAttribute(gemm_bf<2>, cudaFuncAttributeMaxDynamicSharedMemorySize, GEMM_SMEM);

    const int M  = TNODES;
    const int MB = (M + 127) / 128;   // 663

    // CSR of the shared base graph
    detect_kernel<<<1, 32>>>(ei32);
    csr_zero<<<1, 1024>>>();
    csr_hist<<<(EE + 255) / 256, 256>>>(ei32);
    csr_scan<<<1, 1024>>>();
    csr_fill<<<(EE + NN + 255) / 256, 256>>>(ei32);

    // Operand prep
    {
        size_t n = (size_t)TNODES * DD;
        convert_split<<<(unsigned)((n / 4 + 255) / 256), 256>>>(x, p_xhi, p_xlo, n);
        dim3 blk(32, 8);
        transpose_split<<<dim3(4, 4),  blk>>>(Wl, p_wch, p_wcl, DD, DD);
        transpose_split<<<dim3(4, 4),  blk>>>(Wr, p_wch + DD * DD, p_wcl + DD * DD, DD, DD);
        transpose_split<<<dim3(64, 4), blk>>>(W1, p_w1h, p_w1l, DD, FFD);
        transpose_split<<<dim3(4, 64), blk>>>(W2, p_w2h, p_w2l, FFD, DD);
    }

    // fused projection: [xl | xr] = x @ [Wl | Wr]
    {
        dim3 grid(2, MB);
        gemm_bf<2><<<grid, 256, GEMM_SMEM>>>(
            p_xhi, p_xlo, DD, p_wch, p_wcl, DD, bl, br,
            p_xl, p_xr, nullptr, nullptr, DD, M, DD);
    }

    // fused GAT attention + aggregation + LN1
    gat_fused_kernel<<<TNODES, 128>>>(att, x, bias_gat, g1, be1);

    // FFN
    {
        dim3 grid1(FFD / 128, MB);
        gemm_bf<1><<<grid1, 256, GEMM_SMEM>>>(
            p_hhi, p_hlo, DD, p_w1h, p_w1l, DD, b1, nullptr,
            nullptr, nullptr, p_hidh, p_hidl, FFD, M, DD);
        dim3 grid2(1, MB);
        gemm_bf<0><<<grid2, 256, GEMM_SMEM>>>(
            p_hidh, p_hidl, FFD, p_w2h, p_w2l, FFD, b2, nullptr,
            out, nullptr, nullptr, nullptr, DD, M, FFD);
    }

    // LN2 -> final output
    ln2_kernel<<<(TNODES + 7) / 8, 256>>>(out, g2, be2);
}

// round 11
// speedup vs baseline: 2.7939x; 1.1253x over previous
#include <cuda_runtime.h>
#include <cuda_bf16.h>
#include <math.h>
#include <stdint.h>

// ---------------- Problem constants ----------------
#define BB   8
#define TT   12
#define NN   883
#define DD   128
#define HH   8
#define CC   16
#define EE   7000
#define FFD  2048
#define NEG_SLOPE 0.2f

#define BT      (BB*TT)                 // 96
#define TNODES  (BT*NN)                 // 84768
#define MAXDEG  128

typedef __nv_bfloat16 bf16;
typedef __nv_bfloat162 bf162;

// ---------------- Device scratch ----------------
__device__ bf16  g_xhi[(size_t)TNODES * DD];
__device__ bf16  g_xlo[(size_t)TNODES * DD];
__device__ bf16  g_wcT_h[2 * DD * DD];            // [Wl^T ; Wr^T]  256 x 128
__device__ bf16  g_wcT_l[2 * DD * DD];
__device__ bf16  g_w1T_h[(size_t)FFD * DD];
__device__ bf16  g_w1T_l[(size_t)FFD * DD];
__device__ bf16  g_w2T_h[(size_t)DD * FFD];
__device__ bf16  g_w2T_l[(size_t)DD * FFD];
__device__ float g_xl[(size_t)TNODES * DD];
__device__ float g_xr[(size_t)TNODES * DD];
__device__ bf16  g_hhi[(size_t)TNODES * DD];
__device__ bf16  g_hlo[(size_t)TNODES * DD];
__device__ bf16  g_hidhi[(size_t)TNODES * FFD];
__device__ bf16  g_hidlo[(size_t)TNODES * FFD];
__device__ int   g_is64;
// CSR of the shared base graph
__device__ int   g_deg[NN];
__device__ int   g_rowptr[NN + 1];
__device__ int   g_ecnt[NN];
__device__ int   g_esrc[EE + NN];

// ---------------- Helpers ----------------
__device__ __forceinline__ uint32_t smem_to_u32(const void* p) {
    uint32_t a;
    asm("{ .reg .u64 t; cvta.to.shared.u64 t, %1; cvt.u32.u64 %0, t; }"
        : "=r"(a) : "l"(p));
    return a;
}
__device__ __forceinline__ void cp_async16(uint32_t saddr, const void* g, int src_bytes) {
    asm volatile("cp.async.cg.shared.global [%0], [%1], 16, %2;"
        :: "r"(saddr), "l"(g), "r"(src_bytes) : "memory");
}
#define CP_COMMIT() asm volatile("cp.async.commit_group;" ::: "memory")
#define CP_WAIT(N)  asm volatile("cp.async.wait_group %0;" :: "n"(N) : "memory")

__device__ __forceinline__ void ldsm_x4(uint32_t& r0, uint32_t& r1,
                                        uint32_t& r2, uint32_t& r3, uint32_t addr) {
    asm volatile("ldmatrix.sync.aligned.m8n8.x4.shared.b16 {%0,%1,%2,%3}, [%4];"
        : "=r"(r0), "=r"(r1), "=r"(r2), "=r"(r3) : "r"(addr));
}
__device__ __forceinline__ void ldsm_x2(uint32_t& r0, uint32_t& r1, uint32_t addr) {
    asm volatile("ldmatrix.sync.aligned.m8n8.x2.shared.b16 {%0,%1}, [%2];"
        : "=r"(r0), "=r"(r1) : "r"(addr));
}
__device__ __forceinline__ void mma_bf16(float* c,
                                         uint32_t a0, uint32_t a1, uint32_t a2, uint32_t a3,
                                         uint32_t b0, uint32_t b1) {
    asm volatile("mma.sync.aligned.m16n8k16.row.col.f32.bf16.bf16.f32 "
        "{%0,%1,%2,%3}, {%4,%5,%6,%7}, {%8,%9}, {%0,%1,%2,%3};"
        : "+f"(c[0]), "+f"(c[1]), "+f"(c[2]), "+f"(c[3])
        : "r"(a0), "r"(a1), "r"(a2), "r"(a3), "r"(b0), "r"(b1));
}
__device__ __forceinline__ bf16 bf_hi(float v) { return __float2bfloat16_rn(v); }

// ---------------- Pure-bf16 pipelined tensor GEMM ----------------
// MODE 0: C = A@B^T + bias (fp32)   MODE 1: relu->split bf16   MODE 2: dual proj
#define SROW 40
#define TILE_E (128 * SROW)
#define STAGE_E (4 * TILE_E)
#define GEMM_SMEM (2 * STAGE_E * 2)

template<int MODE>
__global__ __launch_bounds__(256, 2)
void gemm_bf(const bf16* __restrict__ Ah, const bf16* __restrict__ Al, int lda,
             const bf16* __restrict__ Bh, const bf16* __restrict__ Bl, int ldb,
             const float* __restrict__ bias, const float* __restrict__ bias2,
             float* __restrict__ C, float* __restrict__ C2,
             bf16* __restrict__ Chi, bf16* __restrict__ Clo,
             int ldc, int M, int K)
{
    extern __shared__ bf16 sm[];
    const uint32_t sbase = smem_to_u32(sm);

    const int tid  = threadIdx.x;
    const int wid  = tid >> 5;
    const int lane = tid & 31;
    const int m0 = blockIdx.y * 128;
    const int n0 = blockIdx.x * 128;

    const int warp_m = (wid >> 2) * 64;
    const int warp_n = (wid & 3) * 32;

    float c[4][4][4];
    #pragma unroll
    for (int i = 0; i < 4; i++)
        #pragma unroll
        for (int j = 0; j < 4; j++)
            #pragma unroll
            for (int r = 0; r < 4; r++) c[i][j][r] = 0.0f;

    const int a_row_l = lane & 15;
    const int a_colh  = (lane >> 4) * 8;
    const int l16     = lane & 15;
    const int b_row_l = l16 & 7;
    const int b_colh  = ((l16 >> 3) & 1) * 8;

    const int nk = K >> 5;

    auto load_stage = [&](int stage, int kc) {
        const int kbase = kc << 5;
        const uint32_t sst = sbase + (uint32_t)stage * STAGE_E * 2;
        #pragma unroll
        for (int t = 0; t < 8; t++) {
            int idx  = t * 256 + tid;
            int tile = idx >> 9;
            int rc   = idx & 511;
            int r    = rc >> 2;
            int cc   = rc & 3;
            uint32_t sa = sst + (uint32_t)(tile * TILE_E + r * SROW + cc * 8) * 2;
            const bf16* gp;
            int bytes = 16;
            if (tile < 2) {
                const bf16* base = (tile == 0) ? Ah : Al;
                int m = m0 + r;
                gp = base + (size_t)m * lda + kbase + cc * 8;
                if (m >= M) bytes = 0;
            } else {
                const bf16* base = (tile == 2) ? Bh : Bl;
                gp = base + (size_t)(n0 + r) * ldb + kbase + cc * 8;
            }
            cp_async16(sa, gp, bytes);
        }
        CP_COMMIT();
    };

    load_stage(0, 0);

    #pragma unroll 1
    for (int kc = 0; kc < nk; kc++) {
        const int cur = kc & 1;
        if (kc + 1 < nk) {
            load_stage(cur ^ 1, kc + 1);
            CP_WAIT(1);
        } else {
            CP_WAIT(0);
        }
        __syncthreads();

        const uint32_t uAh = sbase + (uint32_t)(cur * STAGE_E) * 2;
        const uint32_t uAl = uAh + TILE_E * 2;
        const uint32_t uBh = uAl + TILE_E * 2;
        const uint32_t uBl = uBh + TILE_E * 2;

        #pragma unroll
        for (int kk = 0; kk < 32; kk += 16) {
            uint32_t ah[4][4], al[4][4];
            #pragma unroll
            for (int i = 0; i < 4; i++) {
                uint32_t off = ((uint32_t)((warp_m + i * 16 + a_row_l) * SROW + a_colh + kk)) * 2;
                ldsm_x4(ah[i][0], ah[i][1], ah[i][2], ah[i][3], uAh + off);
                ldsm_x4(al[i][0], al[i][1], al[i][2], al[i][3], uAl + off);
            }
            #pragma unroll
            for (int j = 0; j < 4; j++) {
                uint32_t boff = ((uint32_t)((warp_n + j * 8 + b_row_l) * SROW + b_colh + kk)) * 2;
                uint32_t bh0, bh1, bl0, bl1;
                ldsm_x2(bh0, bh1, uBh + boff);
                ldsm_x2(bl0, bl1, uBl + boff);
                #pragma unroll
                for (int i = 0; i < 4; i++) {
                    mma_bf16(c[i][j], ah[i][0], ah[i][1], ah[i][2], ah[i][3], bh0, bh1);
                    mma_bf16(c[i][j], ah[i][0], ah[i][1], ah[i][2], ah[i][3], bl0, bl1);
                    mma_bf16(c[i][j], al[i][0], al[i][1], al[i][2], al[i][3], bh0, bh1);
                }
            }
        }
        __syncthreads();
    }

    // ---- epilogue ----
    #pragma unroll
    for (int j = 0; j < 4; j++) {
        int colg = n0 + warp_n + j * 8 + (lane & 3) * 2;
        float*       Cp = C;
        const float* bp = bias;
        int col = colg;
        if (MODE == 2 && colg >= 128) { Cp = C2; bp = bias2; col = colg - 128; }
        float bx = bp[col], by = bp[col + 1];
        #pragma unroll
        for (int i = 0; i < 4; i++) {
            int row = m0 + warp_m + i * 16 + (lane >> 2);
            float v0 = c[i][j][0] + bx, v1 = c[i][j][1] + by;
            float v2 = c[i][j][2] + bx, v3 = c[i][j][3] + by;
            if (MODE == 1) {
                v0 = fmaxf(v0, 0.f); v1 = fmaxf(v1, 0.f);
                v2 = fmaxf(v2, 0.f); v3 = fmaxf(v3, 0.f);
                bf16 h0 = bf_hi(v0), h1 = bf_hi(v1), h2 = bf_hi(v2), h3 = bf_hi(v3);
                bf162 hi01; hi01.x = h0; hi01.y = h1;
                bf162 hi23; hi23.x = h2; hi23.y = h3;
                bf162 lo01; lo01.x = bf_hi(v0 - __bfloat162float(h0));
                            lo01.y = bf_hi(v1 - __bfloat162float(h1));
                bf162 lo23; lo23.x = bf_hi(v2 - __bfloat162float(h2));
                            lo23.y = bf_hi(v3 - __bfloat162float(h3));
                if (row < M) {
                    *(bf162*)&Chi[(size_t)row * ldc + col] = hi01;
                    *(bf162*)&Clo[(size_t)row * ldc + col] = lo01;
                }
                if (row + 8 < M) {
                    *(bf162*)&Chi[(size_t)(row + 8) * ldc + col] = hi23;
                    *(bf162*)&Clo[(size_t)(row + 8) * ldc + col] = lo23;
                }
            } else {
                int ld = (MODE == 2) ? DD : ldc;
                if (row < M)     *(float2*)&Cp[(size_t)row * ld + col]       = make_float2(v0, v1);
                if (row + 8 < M) *(float2*)&Cp[(size_t)(row + 8) * ld + col] = make_float2(v2, v3);
            }
        }
    }
}

// ---------------- Operand preparation ----------------
__global__ void convert_split(const float* __restrict__ in,
                              bf16* __restrict__ hi, bf16* __restrict__ lo, size_t n)
{
    size_t i = ((size_t)blockIdx.x * blockDim.x + threadIdx.x) * 4;
    if (i >= n) return;
    float4 v = *(const float4*)&in[i];
    bf16 h0 = bf_hi(v.x), h1 = bf_hi(v.y), h2 = bf_hi(v.z), h3 = bf_hi(v.w);
    bf162 a; a.x = h0; a.y = h1;
    bf162 b; b.x = h2; b.y = h3;
    *(bf162*)&hi[i]     = a;
    *(bf162*)&hi[i + 2] = b;
    bf162 c; c.x = bf_hi(v.x - __bfloat162float(h0)); c.y = bf_hi(v.y - __bfloat162float(h1));
    bf162 d; d.x = bf_hi(v.z - __bfloat162float(h2)); d.y = bf_hi(v.w - __bfloat162float(h3));
    *(bf162*)&lo[i]     = c;
    *(bf162*)&lo[i + 2] = d;
}

__global__ void transpose_split(const float* __restrict__ in,
                                bf16* __restrict__ oh, bf16* __restrict__ ol,
                                int K, int N)
{
    __shared__ float t[32][33];
    int n0 = blockIdx.x * 32, k0 = blockIdx.y * 32;
    int tx = threadIdx.x, ty = threadIdx.y;
    #pragma unroll
    for (int r = 0; r < 4; r++)
        t[ty + r * 8][tx] = in[(size_t)(k0 + ty + r * 8) * N + n0 + tx];
    __syncthreads();
    #pragma unroll
    for (int r = 0; r < 4; r++) {
        int n = n0 + ty + r * 8;
        int k = k0 + tx;
        float v = t[tx][ty + r * 8];
        bf16 h = bf_hi(v);
        oh[(size_t)n * K + k] = h;
        ol[(size_t)n * K + k] = bf_hi(v - __bfloat162float(h));
    }
}

// ---------------- Edge decode + CSR build ----------------
__global__ void detect_kernel(const int* __restrict__ ei32) {
    if (threadIdx.x == 0 && blockIdx.x == 0) {
        int ok = 1;
        #pragma unroll
        for (int i = 1; i < 64; i += 2) ok &= (ei32[i] == 0);
        g_is64 = ok;
    }
}
__device__ __forceinline__ int load_ei(const int* __restrict__ ei32, int is64, int idx) {
    int v = is64 ? ei32[2 * idx] : ei32[idx];
    v = v < 0 ? 0 : (v >= NN ? NN - 1 : v);
    return v;
}

__global__ void csr_zero() {
    int t = blockIdx.x * blockDim.x + threadIdx.x;
    if (t < NN) { g_deg[t] = 1; g_ecnt[t] = 0; }
}
__global__ void csr_hist(const int* __restrict__ ei32) {
    int i = blockIdx.x * blockDim.x + threadIdx.x;
    if (i >= EE) return;
    int dst = load_ei(ei32, g_is64, EE + i);
    atomicAdd(&g_deg[dst], 1);
}
__global__ void csr_scan() {
    __shared__ int tmp[1024];
    int t = threadIdx.x;
    tmp[t] = (t < NN) ? g_deg[t] : 0;
    __syncthreads();
    #pragma unroll
    for (int o = 1; o < 1024; o <<= 1) {
        int u = (t >= o) ? tmp[t - o] : 0;
        __syncthreads();
        tmp[t] += u;
        __syncthreads();
    }
    if (t < NN) g_rowptr[t + 1] = tmp[t];
    if (t == 0) g_rowptr[0] = 0;
}
__global__ void csr_fill(const int* __restrict__ ei32) {
    int i = blockIdx.x * blockDim.x + threadIdx.x;
    if (i >= EE + NN) return;
    int src, dst;
    if (i < EE) {
        src = load_ei(ei32, g_is64, i);
        dst = load_ei(ei32, g_is64, EE + i);
    } else {
        src = dst = i - EE;
    }
    int pos = g_rowptr[dst] + atomicAdd(&g_ecnt[dst], 1);
    g_esrc[pos] = src;
}

// ---------------- Fused GAT softmax+aggregate+LN1 (warp per node) --------------
// block = 256 threads = 8 warps = 8 nodes. lane owns channels [lane*4, lane*4+4),
// head = lane>>2 (4 lanes per head).
__global__ __launch_bounds__(256)
void gat_fused_kernel(const float* __restrict__ att,
                      const float* __restrict__ x,
                      const float* __restrict__ bias_gat,
                      const float* __restrict__ g1,
                      const float* __restrict__ be1)
{
    __shared__ float sc[8][MAXDEG * 8];
    __shared__ int   se[8][MAXDEG];

    const int w    = threadIdx.x >> 5;
    const int lane = threadIdx.x & 31;
    const int node = blockIdx.x * 8 + w;
    const int ch0  = lane * 4;
    const int h    = lane >> 2;
    const int sub  = lane & 3;

    const int inst  = node / NN;
    const int local = node - inst * NN;
    const int ibase = inst * NN;
    const int rs    = g_rowptr[local];
    int deg = g_rowptr[local + 1] - rs;
    if (deg > MAXDEG) deg = MAXDEG;

    // stage neighbor ids (global node index)
    for (int e = lane; e < deg; e += 32)
        se[w][e] = ibase + g_esrc[rs + e];
    __syncwarp();

    const float4 xr4 = *(const float4*)&g_xr[(size_t)node * DD + ch0];
    const float4 at4 = *(const float4*)&att[ch0];
    float* scw = sc[w];

    // ---- pass 1: scores + per-head max ----
    float m = -INFINITY;
    for (int e = 0; e < deg; e++) {
        const float4 xl4 = *(const float4*)&g_xl[(size_t)se[w][e] * DD + ch0];
        float v0 = xl4.x + xr4.x; v0 = v0 > 0.f ? v0 : NEG_SLOPE * v0;
        float v1 = xl4.y + xr4.y; v1 = v1 > 0.f ? v1 : NEG_SLOPE * v1;
        float v2 = xl4.z + xr4.z; v2 = v2 > 0.f ? v2 : NEG_SLOPE * v2;
        float v3 = xl4.w + xr4.w; v3 = v3 > 0.f ? v3 : NEG_SLOPE * v3;
        float p = at4.x * v0;
        p = fmaf(at4.y, v1, p);
        p = fmaf(at4.z, v2, p);
        p = fmaf(at4.w, v3, p);
        p += __shfl_xor_sync(0xffffffffu, p, 1);
        p += __shfl_xor_sync(0xffffffffu, p, 2);
        if (sub == 0) scw[e * 8 + h] = p;
        m = fmaxf(m, p);
    }
    __syncwarp();

    // ---- pass 2: exp + denom (lane-parallel over edges) ----
    float s = 0.f;
    for (int e = sub; e < deg; e += 4) {
        float a = __expf(scw[e * 8 + h] - m);
        scw[e * 8 + h] = a;
        s += a;
    }
    __syncwarp();
    s += __shfl_xor_sync(0xffffffffu, s, 1);
    s += __shfl_xor_sync(0xffffffffu, s, 2);
    const float inv_s = 1.0f / s;

    // ---- pass 3: aggregate ----
    float a0 = 0.f, a1 = 0.f, a2 = 0.f, a3 = 0.f;
    for (int e = 0; e < deg; e++) {
        const float alpha = scw[e * 8 + h] * inv_s;
        const float4 xl4 = *(const float4*)&g_xl[(size_t)se[w][e] * DD + ch0];
        a0 = fmaf(alpha, xl4.x, a0);
        a1 = fmaf(alpha, xl4.y, a1);
        a2 = fmaf(alpha, xl4.z, a2);
        a3 = fmaf(alpha, xl4.w, a3);
    }

    // ---- LN1 (warp butterfly) ----
    const float4 xv = *(const float4*)&x[(size_t)node * DD + ch0];
    const float4 bg = *(const float4*)&bias_gat[ch0];
    float v0 = xv.x + a0 + bg.x;
    float v1 = xv.y + a1 + bg.y;
    float v2 = xv.z + a2 + bg.z;
    float v3 = xv.w + a3 + bg.w;

    float sum = v0 + v1 + v2 + v3;
    #pragma unroll
    for (int o = 16; o > 0; o >>= 1) sum += __shfl_xor_sync(0xffffffffu, sum, o);
    const float mu = sum * (1.0f / DD);

    float d0 = v0 - mu, d1 = v1 - mu, d2 = v2 - mu, d3 = v3 - mu;
    float sq = d0 * d0 + d1 * d1 + d2 * d2 + d3 * d3;
    #pragma unroll
    for (int o = 16; o > 0; o >>= 1) sq += __shfl_xor_sync(0xffffffffu, sq, o);
    const float rstd = rsqrtf(sq * (1.0f / DD) + 1e-5f);

    const float4 gv = *(const float4*)&g1[ch0];
    const float4 bv = *(const float4*)&be1[ch0];
    float h0 = d0 * rstd * gv.x + bv.x;
    float h1 = d1 * rstd * gv.y + bv.y;
    float h2 = d2 * rstd * gv.z + bv.z;
    float h3 = d3 * rstd * gv.w + bv.w;

    bf16 b0 = bf_hi(h0), b1 = bf_hi(h1), b2 = bf_hi(h2), b3 = bf_hi(h3);
    bf162 hi01; hi01.x = b0; hi01.y = b1;
    bf162 hi23; hi23.x = b2; hi23.y = b3;
    bf162 lo01; lo01.x = bf_hi(h0 - __bfloat162float(b0));
                lo01.y = bf_hi(h1 - __bfloat162float(b1));
    bf162 lo23; lo23.x = bf_hi(h2 - __bfloat162float(b2));
                lo23.y = bf_hi(h3 - __bfloat162float(b3));
    size_t base = (size_t)node * DD + ch0;
    *(bf162*)&g_hhi[base]     = hi01;
    *(bf162*)&g_hhi[base + 2] = hi23;
    *(bf162*)&g_hlo[base]     = lo01;
    *(bf162*)&g_hlo[base + 2] = lo23;
}

// ---------------- LN2: out = LN((hhi+hlo) + ff), ff staged in d_out -------------
__global__ void ln2_kernel(float* __restrict__ out,
                           const float* __restrict__ g,
                           const float* __restrict__ b)
{
    int row = blockIdx.x * 8 + (threadIdx.x >> 5);
    if (row >= TNODES) return;
    int lane = threadIdx.x & 31;
    size_t base = (size_t)row * DD + lane * 4;

    bf162 h01 = *(const bf162*)&g_hhi[base];
    bf162 h23 = *(const bf162*)&g_hhi[base + 2];
    bf162 l01 = *(const bf162*)&g_hlo[base];
    bf162 l23 = *(const bf162*)&g_hlo[base + 2];
    float4 fv = *(const float4*)&out[base];
    float v[4];
    v[0] = __bfloat162float(h01.x) + __bfloat162float(l01.x) + fv.x;
    v[1] = __bfloat162float(h01.y) + __bfloat162float(l01.y) + fv.y;
    v[2] = __bfloat162float(h23.x) + __bfloat162float(l23.x) + fv.z;
    v[3] = __bfloat162float(h23.y) + __bfloat162float(l23.y) + fv.w;

    float s = v[0] + v[1] + v[2] + v[3];
    #pragma unroll
    for (int o = 16; o > 0; o >>= 1) s += __shfl_xor_sync(0xffffffffu, s, o);
    float mu = s * (1.0f / DD);

    float sq = 0.f;
    #pragma unroll
    for (int i = 0; i < 4; i++) { float d = v[i] - mu; sq += d * d; }
    #pragma unroll
    for (int o = 16; o > 0; o >>= 1) sq += __shfl_xor_sync(0xffffffffu, sq, o);
    float rstd = rsqrtf(sq * (1.0f / DD) + 1e-5f);

    float4 gv = *(const float4*)&g[lane * 4];
    float4 bv = *(const float4*)&b[lane * 4];
    float4 o4;
    o4.x = (v[0] - mu) * rstd * gv.x + bv.x;
    o4.y = (v[1] - mu) * rstd * gv.y + bv.y;
    o4.z = (v[2] - mu) * rstd * gv.z + bv.z;
    o4.w = (v[3] - mu) * rstd * gv.w + bv.w;
    *(float4*)&out[base] = o4;
}

// ---------------- Launch ----------------
extern "C" void kernel_launch(void* const* d_in, const int* in_sizes, int n_in,
                              void* d_out, int out_size)
{
    const float* x        = (const float*)d_in[0];
    const int*   ei32     = (const int*)d_in[1];
    const float* Wl       = (const float*)d_in[2];
    const float* bl       = (const float*)d_in[3];
    const float* Wr       = (const float*)d_in[4];
    const float* br       = (const float*)d_in[5];
    const float* att      = (const float*)d_in[6];
    const float* bias_gat = (const float*)d_in[7];
    const float* W1       = (const float*)d_in[8];
    const float* b1       = (const float*)d_in[9];
    const float* W2       = (const float*)d_in[10];
    const float* b2       = (const float*)d_in[11];
    const float* g1       = (const float*)d_in[12];
    const float* be1      = (const float*)d_in[13];
    const float* g2       = (const float*)d_in[14];
    const float* be2      = (const float*)d_in[15];
    float*       out      = (float*)d_out;

    bf16 *p_xhi, *p_xlo, *p_wch, *p_wcl, *p_w1h, *p_w1l, *p_w2h, *p_w2l;
    bf16 *p_hhi, *p_hlo, *p_hidh, *p_hidl;
    float *p_xl, *p_xr;
    cudaGetSymbolAddress((void**)&p_xhi,  g_xhi);
    cudaGetSymbolAddress((void**)&p_xlo,  g_xlo);
    cudaGetSymbolAddress((void**)&p_wch,  g_wcT_h);
    cudaGetSymbolAddress((void**)&p_wcl,  g_wcT_l);
    cudaGetSymbolAddress((void**)&p_w1h,  g_w1T_h);
    cudaGetSymbolAddress((void**)&p_w1l,  g_w1T_l);
    cudaGetSymbolAddress((void**)&p_w2h,  g_w2T_h);
    cudaGetSymbolAddress((void**)&p_w2l,  g_w2T_l);
    cudaGetSymbolAddress((void**)&p_hhi,  g_hhi);
    cudaGetSymbolAddress((void**)&p_hlo,  g_hlo);
    cudaGetSymbolAddress((void**)&p_hidh, g_hidhi);
    cudaGetSymbolAddress((void**)&p_hidl, g_hidlo);
    cudaGetSymbolAddress((void**)&p_xl,   g_xl);
    cudaGetSymbolAddress((void**)&p_xr,   g_xr);

    cudaFuncSetAttribute(gemm_bf<0>, cudaFuncAttributeMaxDynamicSharedMemorySize, GEMM_SMEM);
    cudaFuncSetAttribute(gemm_bf<1>, cudaFuncAttributeMaxDynamicSharedMemorySize, GEMM_SMEM);
    cudaFuncSetAttribute(gemm_bf<2>, cudaFuncAttributeMaxDynamicSharedMemorySize, GEMM_SMEM);

    const int M  = TNODES;
    const int MB = (M + 127) / 128;   // 663

    // CSR of the shared base graph
    detect_kernel<<<1, 32>>>(ei32);
    csr_zero<<<1, 1024>>>();
    csr_hist<<<(EE + 255) / 256, 256>>>(ei32);
    csr_scan<<<1, 1024>>>();
    csr_fill<<<(EE + NN + 255) / 256, 256>>>(ei32);

    // Operand prep
    {
        size_t n = (size_t)TNODES * DD;
        convert_split<<<(unsigned)((n / 4 + 255) / 256), 256>>>(x, p_xhi, p_xlo, n);
        dim3 blk(32, 8);
        transpose_split<<<dim3(4, 4),  blk>>>(Wl, p_wch, p_wcl, DD, DD);
        transpose_split<<<dim3(4, 4),  blk>>>(Wr, p_wch + DD * DD, p_wcl + DD * DD, DD, DD);
        transpose_split<<<dim3(64, 4), blk>>>(W1, p_w1h, p_w1l, DD, FFD);
        transpose_split<<<dim3(4, 64), blk>>>(W2, p_w2h, p_w2l, FFD, DD);
    }

    // fused projection: [xl | xr] = x @ [Wl | Wr]
    {
        dim3 grid(2, MB);
        gemm_bf<2><<<grid, 256, GEMM_SMEM>>>(
            p_xhi, p_xlo, DD, p_wch, p_wcl, DD, bl, br,
            p_xl, p_xr, nullptr, nullptr, DD, M, DD);
    }

    // fused GAT attention + aggregation + LN1 (warp per node)
    gat_fused_kernel<<<TNODES / 8, 256>>>(att, x, bias_gat, g1, be1);

    // FFN
    {
        dim3 grid1(FFD / 128, MB);
        gemm_bf<1><<<grid1, 256, GEMM_SMEM>>>(
            p_hhi, p_hlo, DD, p_w1h, p_w1l, DD, b1, nullptr,
            nullptr, nullptr, p_hidh, p_hidl, FFD, M, DD);
        dim3 grid2(1, MB);
        gemm_bf<0><<<grid2, 256, GEMM_SMEM>>>(
            p_hidh, p_hidl, FFD, p_w2h, p_w2l, FFD, b2, nullptr,
            out, nullptr, nullptr, nullptr, DD, M, FFD);
    }

    // LN2 -> final output
    ln2_kernel<<<(TNODES + 7) / 8, 256>>>(out, g2, be2);
}